// round 1
// baseline (speedup 1.0000x reference)
#include <cuda_runtime.h>
#include <math.h>

#define BB   4
#define TT   8
#define NN   2000
#define FIN  158
#define DD   128
#define HH   4
#define CC   32
#define MAXDEG 256
#define ROWS (BB*NN)

// ---------------- device scratch (no allocs allowed) ----------------
__device__ float g_h  [ROWS*DD];   // post LN/ReLU features (layer-0 input)
__device__ float g_h2 [ROWS*DD];   // after residual+elu (layer-1 input)
__device__ float g_xh [ROWS*DD];   // current layer's projected features
__device__ float g_es [ROWS*HH];   // e_src per node/head
__device__ float g_ed [ROWS*HH];   // e_dst per node/head
__device__ int   g_adj[ROWS*MAXDEG];
__device__ int   g_deg[ROWS];
__device__ float g_hf [ROWS*CC];   // layer-1 output (head-mean)

// ---------------- kernel A: x@W_in + b_in, LayerNorm, ReLU ----------------
__global__ void k_inproj(const float* __restrict__ x_alpha,
                         const float* __restrict__ W_in,
                         const float* __restrict__ b_in,
                         const float* __restrict__ ln_g,
                         const float* __restrict__ ln_b)
{
    int row = blockIdx.x;              // b*NN + n
    int b = row / NN, n = row % NN;
    int d = threadIdx.x;               // 0..127
    __shared__ float xr[FIN];
    __shared__ float red[4];

    const float* xp = x_alpha + (((size_t)b*TT + (TT-1))*NN + n)*FIN;
    for (int k = d; k < FIN; k += DD) xr[k] = xp[k];
    __syncthreads();

    float acc = b_in[d];
    #pragma unroll 2
    for (int k = 0; k < FIN; ++k) acc = fmaf(xr[k], W_in[k*DD + d], acc);

    // mean over 128
    float s = acc;
    for (int o = 16; o; o >>= 1) s += __shfl_xor_sync(0xffffffffu, s, o);
    if ((d & 31) == 0) red[d >> 5] = s;
    __syncthreads();
    float mean = (red[0] + red[1] + red[2] + red[3]) * (1.0f/DD);
    __syncthreads();

    float dv = acc - mean;
    float s2 = dv * dv;
    for (int o = 16; o; o >>= 1) s2 += __shfl_xor_sync(0xffffffffu, s2, o);
    if ((d & 31) == 0) red[d >> 5] = s2;
    __syncthreads();
    float var = (red[0] + red[1] + red[2] + red[3]) * (1.0f/DD);

    float y = dv * rsqrtf(var + 1e-5f) * ln_g[d] + ln_b[d];
    g_h[row*DD + d] = fmaxf(y, 0.0f);
}

// ---------------- kernel B: adjacency list build ----------------
__global__ void k_adj(const float* __restrict__ sg)
{
    int row = blockIdx.x;              // b*NN + i
    int b = row / NN, i = row % NN;
    __shared__ int cnt;
    if (threadIdx.x == 0) cnt = 0;
    __syncthreads();

    const float* rp = sg + ((size_t)b*NN + i)*NN;
    for (int j = threadIdx.x; j < NN; j += blockDim.x) {
        if (rp[j] > 0.0f || j == i) {
            int k = atomicAdd(&cnt, 1);
            if (k < MAXDEG) g_adj[row*MAXDEG + k] = j;
        }
    }
    __syncthreads();
    if (threadIdx.x == 0) g_deg[row] = cnt < MAXDEG ? cnt : MAXDEG;
}

// ---------------- kernel C: xh = h@W ; e_src/e_dst per head ----------------
__global__ void k_proj_att(const float* __restrict__ hin,
                           const float* __restrict__ W,
                           const float* __restrict__ as_,
                           const float* __restrict__ ad_)
{
    int row = blockIdx.x;
    int d = threadIdx.x;
    __shared__ float hr[DD];
    hr[d] = hin[row*DD + d];
    __syncthreads();

    float acc = 0.0f;
    #pragma unroll 4
    for (int k = 0; k < DD; ++k) acc = fmaf(hr[k], W[k*DD + d], acc);
    g_xh[row*DD + d] = acc;

    int h = d >> 5;
    float es = acc * as_[d];           // as_[h*32+c] == as_[d]
    for (int o = 16; o; o >>= 1) es += __shfl_xor_sync(0xffffffffu, es, o);
    float ed = acc * ad_[d];
    for (int o = 16; o; o >>= 1) ed += __shfl_xor_sync(0xffffffffu, ed, o);
    if ((d & 31) == 0) { g_es[row*HH + h] = es; g_ed[row*HH + h] = ed; }
}

// ---------------- kernel D: sparse softmax + aggregate + epilogue ----------
// MODE 0: hout[row] = hin[row] + elu(agg + bias[128])      (layer 0, concat)
// MODE 1: g_hf[row] = mean_over_heads(agg) + bias[32]      (layer 1)
template <int MODE>
__global__ void k_gat(const float* __restrict__ hin,
                      const float* __restrict__ bias,
                      float* __restrict__ hout)
{
    int row = blockIdx.x;
    int b = row / NN;
    int tid = threadIdx.x;             // 0..127
    int h = tid >> 5, lane = tid & 31;

    __shared__ int   sdeg;
    __shared__ int   sidx[MAXDEG];
    __shared__ float salp[MAXDEG*HH];  // [k][h]
    __shared__ float sinv[HH];
    __shared__ float sed[HH];
    __shared__ float souts[DD];

    if (tid == 0) sdeg = g_deg[row];
    if (tid < HH) sed[tid] = g_ed[row*HH + tid];
    __syncthreads();
    int deg = sdeg;

    for (int k = tid; k < deg; k += DD) sidx[k] = g_adj[row*MAXDEG + k];
    __syncthreads();

    // scores: s = leakyrelu(e_dst[i,h] + e_src[j,h], 0.2)
    for (int t = tid; t < deg*HH; t += DD) {
        int k = t >> 2, hh = t & 3;
        float s = sed[hh] + g_es[((size_t)b*NN + sidx[k])*HH + hh];
        s = s >= 0.0f ? s : 0.2f * s;
        salp[k*HH + hh] = s;
    }
    __syncthreads();

    // per-head softmax: warp h owns head h
    {
        float m = -INFINITY;
        for (int k = lane; k < deg; k += 32) m = fmaxf(m, salp[k*HH + h]);
        for (int o = 16; o; o >>= 1) m = fmaxf(m, __shfl_xor_sync(0xffffffffu, m, o));
        float sum = 0.0f;
        for (int k = lane; k < deg; k += 32) {
            float e = expf(salp[k*HH + h] - m);
            salp[k*HH + h] = e;
            sum += e;
        }
        for (int o = 16; o; o >>= 1) sum += __shfl_xor_sync(0xffffffffu, sum, o);
        if (lane == 0) sinv[h] = 1.0f / sum;
    }
    __syncthreads();

    // aggregate: thread tid = (h, c); coalesced 512B gathers of xh rows
    float acc = 0.0f;
    for (int k = 0; k < deg; ++k)
        acc = fmaf(salp[k*HH + h], g_xh[((size_t)b*NN + sidx[k])*DD + tid], acc);
    acc *= sinv[h];

    if (MODE == 0) {
        float o0 = acc + bias[tid];
        float e = o0 > 0.0f ? o0 : (expf(o0) - 1.0f);   // elu, alpha=1
        hout[row*DD + tid] = hin[row*DD + tid] + e;
    } else {
        souts[tid] = acc;
        __syncthreads();
        if (tid < CC) {
            float m4 = 0.25f * (souts[tid] + souts[32+tid] + souts[64+tid] + souts[96+tid]);
            g_hf[row*CC + tid] = m4 + bias[tid];
        }
    }
}

// ---------------- kernel E: out = hf @ W_out + b_out ----------------
__global__ void k_out(const float* __restrict__ Wout,
                      const float* __restrict__ bout,
                      float* __restrict__ out)
{
    int row = blockIdx.x;
    int d = threadIdx.x;
    __shared__ float hr[CC];
    if (d < CC) hr[d] = g_hf[row*CC + d];
    __syncthreads();
    float acc = bout[d];
    #pragma unroll
    for (int k = 0; k < CC; ++k) acc = fmaf(hr[k], Wout[k*DD + d], acc);
    out[row*DD + d] = acc;
}

// ---------------- launch ----------------
extern "C" void kernel_launch(void* const* d_in, const int* in_sizes, int n_in,
                              void* d_out, int out_size)
{
    const float* x_alpha = (const float*)d_in[0];
    const float* sg      = (const float*)d_in[1];
    const float* W_in    = (const float*)d_in[2];
    const float* b_in    = (const float*)d_in[3];
    const float* ln_g    = (const float*)d_in[4];
    const float* ln_b    = (const float*)d_in[5];
    const float* W0      = (const float*)d_in[6];
    const float* as0     = (const float*)d_in[7];
    const float* ad0     = (const float*)d_in[8];
    const float* bias0   = (const float*)d_in[9];
    const float* W1      = (const float*)d_in[10];
    const float* as1     = (const float*)d_in[11];
    const float* ad1     = (const float*)d_in[12];
    const float* bias1   = (const float*)d_in[13];
    const float* W_out   = (const float*)d_in[14];
    const float* b_out   = (const float*)d_in[15];
    float* out = (float*)d_out;

    float *h, *h2;
    cudaGetSymbolAddress((void**)&h,  g_h);
    cudaGetSymbolAddress((void**)&h2, g_h2);

    k_inproj<<<ROWS, DD>>>(x_alpha, W_in, b_in, ln_g, ln_b);
    k_adj<<<ROWS, 256>>>(sg);
    k_proj_att<<<ROWS, DD>>>(h, W0, as0, ad0);
    k_gat<0><<<ROWS, DD>>>(h, bias0, h2);
    k_proj_att<<<ROWS, DD>>>(h2, W1, as1, ad1);
    k_gat<1><<<ROWS, DD>>>(nullptr, bias1, nullptr);
    k_out<<<ROWS, DD>>>(W_out, b_out, out);
}

// round 3
// speedup vs baseline: 1.1803x; 1.1803x over previous
#include <cuda_runtime.h>
#include <math.h>

#define BB   4
#define TT   8
#define NN   2000
#define FIN  158
#define DD   128
#define HH   4
#define CC   32
#define MAXDEG 256
#define ROWS (BB*NN)

// ---------------- device scratch ----------------
__device__ float  g_h  [ROWS*DD];
__device__ float  g_h2 [ROWS*DD];
__device__ float  g_xh [ROWS*DD];
__device__ float4 g_es4[ROWS];
__device__ float4 g_ed4[ROWS];
__device__ int    g_adj[ROWS*MAXDEG];
__device__ int    g_deg[ROWS];
__device__ float  g_hf [ROWS*CC];

// ============ kernel 1 (fused): input proj+LN+ReLU  ||  adjacency build ============
// blocks [0,500): inproj, 16 rows/block, 256 thr (warp -> 2 rows, thread -> 4 dims)
// blocks [500,8500): adjacency row scan
__global__ void k_front(const float* __restrict__ x_alpha,
                        const float* __restrict__ W_in,
                        const float* __restrict__ b_in,
                        const float* __restrict__ ln_g,
                        const float* __restrict__ ln_b,
                        const float* __restrict__ sg)
{
    int tid = threadIdx.x;
    if (blockIdx.x < 500) {
        __shared__ float xr[16][FIN];
        int row0 = blockIdx.x * 16;
        #pragma unroll
        for (int r = 0; r < 16; ++r) {
            int row = row0 + r;
            int b = row / NN, n = row % NN;
            const float* xp = x_alpha + (((size_t)b*TT + (TT-1))*NN + n)*FIN;
            for (int k = tid; k < FIN; k += 256) xr[r][k] = xp[k];
        }
        __syncthreads();

        int w = tid >> 5, lane = tid & 31;
        int r0 = 2*w, r1 = 2*w + 1;
        float4 bi = *(const float4*)(b_in + 4*lane);
        float4 a0 = bi, a1 = bi;
        #pragma unroll 8
        for (int k = 0; k < FIN; ++k) {
            float4 wv = *(const float4*)(W_in + k*DD + 4*lane);
            float x0 = xr[r0][k], x1 = xr[r1][k];
            a0.x = fmaf(x0, wv.x, a0.x); a0.y = fmaf(x0, wv.y, a0.y);
            a0.z = fmaf(x0, wv.z, a0.z); a0.w = fmaf(x0, wv.w, a0.w);
            a1.x = fmaf(x1, wv.x, a1.x); a1.y = fmaf(x1, wv.y, a1.y);
            a1.z = fmaf(x1, wv.z, a1.z); a1.w = fmaf(x1, wv.w, a1.w);
        }
        float4 gg = *(const float4*)(ln_g + 4*lane);
        float4 gb = *(const float4*)(ln_b + 4*lane);

        // LN + ReLU per row (row lives entirely in one warp)
        {
            float s = a0.x + a0.y + a0.z + a0.w;
            for (int o = 16; o; o >>= 1) s += __shfl_xor_sync(0xffffffffu, s, o);
            float mean = s * (1.0f/DD);
            float dx = a0.x-mean, dy = a0.y-mean, dz = a0.z-mean, dw = a0.w-mean;
            float q = dx*dx + dy*dy + dz*dz + dw*dw;
            for (int o = 16; o; o >>= 1) q += __shfl_xor_sync(0xffffffffu, q, o);
            float sc = rsqrtf(q * (1.0f/DD) + 1e-5f);
            float4 y;
            y.x = fmaxf(dx*sc*gg.x + gb.x, 0.f); y.y = fmaxf(dy*sc*gg.y + gb.y, 0.f);
            y.z = fmaxf(dz*sc*gg.z + gb.z, 0.f); y.w = fmaxf(dw*sc*gg.w + gb.w, 0.f);
            *(float4*)(g_h + (size_t)(row0+r0)*DD + 4*lane) = y;
        }
        {
            float s = a1.x + a1.y + a1.z + a1.w;
            for (int o = 16; o; o >>= 1) s += __shfl_xor_sync(0xffffffffu, s, o);
            float mean = s * (1.0f/DD);
            float dx = a1.x-mean, dy = a1.y-mean, dz = a1.z-mean, dw = a1.w-mean;
            float q = dx*dx + dy*dy + dz*dz + dw*dw;
            for (int o = 16; o; o >>= 1) q += __shfl_xor_sync(0xffffffffu, q, o);
            float sc = rsqrtf(q * (1.0f/DD) + 1e-5f);
            float4 y;
            y.x = fmaxf(dx*sc*gg.x + gb.x, 0.f); y.y = fmaxf(dy*sc*gg.y + gb.y, 0.f);
            y.z = fmaxf(dz*sc*gg.z + gb.z, 0.f); y.w = fmaxf(dw*sc*gg.w + gb.w, 0.f);
            *(float4*)(g_h + (size_t)(row0+r1)*DD + 4*lane) = y;
        }
    } else {
        int row = blockIdx.x - 500;           // b*NN + i
        int i = row % NN;
        __shared__ int cnt;
        if (tid == 0) cnt = 0;
        __syncthreads();
        const float4* rp = (const float4*)(sg + (size_t)row*NN);
        for (int t = tid; t < NN/4; t += 256) {
            float4 v = rp[t];
            int j0 = 4*t;
            if (v.x > 0.f || j0   == i) { int k = atomicAdd(&cnt,1); if (k < MAXDEG) g_adj[row*MAXDEG+k] = j0;   }
            if (v.y > 0.f || j0+1 == i) { int k = atomicAdd(&cnt,1); if (k < MAXDEG) g_adj[row*MAXDEG+k] = j0+1; }
            if (v.z > 0.f || j0+2 == i) { int k = atomicAdd(&cnt,1); if (k < MAXDEG) g_adj[row*MAXDEG+k] = j0+2; }
            if (v.w > 0.f || j0+3 == i) { int k = atomicAdd(&cnt,1); if (k < MAXDEG) g_adj[row*MAXDEG+k] = j0+3; }
        }
        __syncthreads();
        if (tid == 0) g_deg[row] = cnt < MAXDEG ? cnt : MAXDEG;
    }
}

// ============ kernel 2/4: xh = h@W ; per-head e_src/e_dst ============
// 8 rows/block, 128 thr: warp -> 2 rows, thread -> 4 output dims
__global__ void k_proj(const float* __restrict__ hin,
                       const float* __restrict__ W,
                       const float* __restrict__ as_,
                       const float* __restrict__ ad_)
{
    __shared__ float hr[8][DD];
    int row0 = blockIdx.x * 8, tid = threadIdx.x;
    #pragma unroll
    for (int r = 0; r < 8; ++r) hr[r][tid] = hin[(size_t)(row0+r)*DD + tid];
    __syncthreads();

    int w = tid >> 5, lane = tid & 31;
    int r0 = 2*w, r1 = 2*w + 1;
    float4 a0 = {0,0,0,0}, a1 = {0,0,0,0};
    #pragma unroll 8
    for (int k = 0; k < DD; ++k) {
        float4 wv = *(const float4*)(W + k*DD + 4*lane);
        float x0 = hr[r0][k], x1 = hr[r1][k];
        a0.x = fmaf(x0, wv.x, a0.x); a0.y = fmaf(x0, wv.y, a0.y);
        a0.z = fmaf(x0, wv.z, a0.z); a0.w = fmaf(x0, wv.w, a0.w);
        a1.x = fmaf(x1, wv.x, a1.x); a1.y = fmaf(x1, wv.y, a1.y);
        a1.z = fmaf(x1, wv.z, a1.z); a1.w = fmaf(x1, wv.w, a1.w);
    }
    *(float4*)(g_xh + (size_t)(row0+r0)*DD + 4*lane) = a0;
    *(float4*)(g_xh + (size_t)(row0+r1)*DD + 4*lane) = a1;

    float4 av = *(const float4*)(as_ + 4*lane);
    float4 dv = *(const float4*)(ad_ + 4*lane);
    float es0 = a0.x*av.x + a0.y*av.y + a0.z*av.z + a0.w*av.w;
    float ed0 = a0.x*dv.x + a0.y*dv.y + a0.z*dv.z + a0.w*dv.w;
    float es1 = a1.x*av.x + a1.y*av.y + a1.z*av.z + a1.w*av.w;
    float ed1 = a1.x*dv.x + a1.y*dv.y + a1.z*dv.z + a1.w*dv.w;
    // reduce within 8-lane (per-head) groups
    for (int o = 4; o; o >>= 1) {
        es0 += __shfl_xor_sync(0xffffffffu, es0, o);
        ed0 += __shfl_xor_sync(0xffffffffu, ed0, o);
        es1 += __shfl_xor_sync(0xffffffffu, es1, o);
        ed1 += __shfl_xor_sync(0xffffffffu, ed1, o);
    }
    if ((lane & 7) == 0) {
        int h = lane >> 3;
        ((float*)(g_es4 + row0 + r0))[h] = es0;
        ((float*)(g_ed4 + row0 + r0))[h] = ed0;
        ((float*)(g_es4 + row0 + r1))[h] = es1;
        ((float*)(g_ed4 + row0 + r1))[h] = ed1;
    }
}

// ============ kernel 3/5: sparse softmax + float4 gather-aggregate ============
// MODE 0: hout = hin + elu(agg + bias[128])   (layer 0)
// MODE 1: g_hf = head-mean(agg) + bias[32]    (layer 1)
template <int MODE>
__global__ void k_gat(const float* __restrict__ hin,
                      const float* __restrict__ bias,
                      float* __restrict__ hout)
{
    int row = blockIdx.x;
    int b = row / NN;
    int tid = threadIdx.x, w = tid >> 5, lane = tid & 31;

    __shared__ int   sdeg;
    __shared__ int   soff[MAXDEG];                     // element offsets into g_xh
    __shared__ __align__(16) float salp[MAXDEG*HH];    // [k][h]
    __shared__ float sinv[HH];
    __shared__ __align__(16) float spart[4][DD];

    if (tid == 0) sdeg = g_deg[row];
    __syncthreads();
    int deg = sdeg;
    int bN = b * NN;
    float4 edv = g_ed4[row];

    // scores
    for (int k = tid; k < deg; k += 128) {
        int j = g_adj[row*MAXDEG + k];
        soff[k] = (bN + j) * DD;
        float4 es = g_es4[bN + j];
        float4 s;
        s.x = edv.x + es.x; s.x = s.x >= 0.f ? s.x : 0.2f*s.x;
        s.y = edv.y + es.y; s.y = s.y >= 0.f ? s.y : 0.2f*s.y;
        s.z = edv.z + es.z; s.z = s.z >= 0.f ? s.z : 0.2f*s.z;
        s.w = edv.w + es.w; s.w = s.w >= 0.f ? s.w : 0.2f*s.w;
        *(float4*)(salp + k*HH) = s;
    }
    __syncthreads();

    // per-head softmax: warp w owns head w
    {
        float m = -1e30f;
        for (int k = lane; k < deg; k += 32) m = fmaxf(m, salp[k*HH + w]);
        for (int o = 16; o; o >>= 1) m = fmaxf(m, __shfl_xor_sync(0xffffffffu, m, o));
        float sum = 0.f;
        for (int k = lane; k < deg; k += 32) {
            float e = expf(salp[k*HH + w] - m);
            salp[k*HH + w] = e;
            sum += e;
        }
        for (int o = 16; o; o >>= 1) sum += __shfl_xor_sync(0xffffffffu, sum, o);
        if (lane == 0) sinv[w] = 1.0f / sum;
    }
    __syncthreads();

    // gather: warp w handles neighbors k = w, w+4, ... ; lane covers dims 4*lane..+3
    const float* base = g_xh + 4*lane;
    int hsel = lane >> 3;
    float4 acc = {0,0,0,0};
    #pragma unroll 2
    for (int k = w; k < deg; k += 4) {
        float a = salp[k*HH + hsel];
        float4 v = *(const float4*)(base + soff[k]);
        acc.x = fmaf(a, v.x, acc.x); acc.y = fmaf(a, v.y, acc.y);
        acc.z = fmaf(a, v.z, acc.z); acc.w = fmaf(a, v.w, acc.w);
    }
    *(float4*)(&spart[w][4*lane]) = acc;
    __syncthreads();

    float v = spart[0][tid] + spart[1][tid] + spart[2][tid] + spart[3][tid];
    v *= sinv[tid >> 5];

    if (MODE == 0) {
        float o0 = v + bias[tid];
        float e = o0 > 0.f ? o0 : (expf(o0) - 1.0f);     // ELU(alpha=1)
        hout[(size_t)row*DD + tid] = hin[(size_t)row*DD + tid] + e;
    } else {
        spart[0][tid] = v;
        __syncthreads();
        if (tid < CC) {
            float m4 = 0.25f * (spart[0][tid] + spart[0][32+tid] + spart[0][64+tid] + spart[0][96+tid]);
            g_hf[(size_t)row*CC + tid] = m4 + bias[tid];
        }
    }
}

// ============ kernel 6: out = hf @ W_out + b_out ============
__global__ void k_out(const float* __restrict__ Wout,
                      const float* __restrict__ bout,
                      float* __restrict__ out)
{
    __shared__ float hr[8*CC];
    int row0 = blockIdx.x * 8, tid = threadIdx.x;
    for (int idx = tid; idx < 8*CC; idx += 128) hr[idx] = g_hf[(size_t)row0*CC + idx];
    __syncthreads();

    int w = tid >> 5, lane = tid & 31;
    int r0 = 2*w, r1 = 2*w + 1;
    float4 bo = *(const float4*)(bout + 4*lane);
    float4 a0 = bo, a1 = bo;
    #pragma unroll
    for (int k = 0; k < CC; ++k) {
        float4 wv = *(const float4*)(Wout + k*DD + 4*lane);
        float x0 = hr[r0*CC + k], x1 = hr[r1*CC + k];
        a0.x = fmaf(x0, wv.x, a0.x); a0.y = fmaf(x0, wv.y, a0.y);
        a0.z = fmaf(x0, wv.z, a0.z); a0.w = fmaf(x0, wv.w, a0.w);
        a1.x = fmaf(x1, wv.x, a1.x); a1.y = fmaf(x1, wv.y, a1.y);
        a1.z = fmaf(x1, wv.z, a1.z); a1.w = fmaf(x1, wv.w, a1.w);
    }
    *(float4*)(out + (size_t)(row0+r0)*DD + 4*lane) = a0;
    *(float4*)(out + (size_t)(row0+r1)*DD + 4*lane) = a1;
}

// ---------------- launch ----------------
extern "C" void kernel_launch(void* const* d_in, const int* in_sizes, int n_in,
                              void* d_out, int out_size)
{
    const float* x_alpha = (const float*)d_in[0];
    const float* sg      = (const float*)d_in[1];
    const float* W_in    = (const float*)d_in[2];
    const float* b_in    = (const float*)d_in[3];
    const float* ln_g    = (const float*)d_in[4];
    const float* ln_b    = (const float*)d_in[5];
    const float* W0      = (const float*)d_in[6];
    const float* as0     = (const float*)d_in[7];
    const float* ad0     = (const float*)d_in[8];
    const float* bias0   = (const float*)d_in[9];
    const float* W1      = (const float*)d_in[10];
    const float* as1     = (const float*)d_in[11];
    const float* ad1     = (const float*)d_in[12];
    const float* bias1   = (const float*)d_in[13];
    const float* W_out   = (const float*)d_in[14];
    const float* b_out   = (const float*)d_in[15];
    float* out = (float*)d_out;

    float *h, *h2;
    cudaGetSymbolAddress((void**)&h,  g_h);
    cudaGetSymbolAddress((void**)&h2, g_h2);

    k_front<<<500 + ROWS, 256>>>(x_alpha, W_in, b_in, ln_g, ln_b, sg);
    k_proj<<<ROWS/8, DD>>>(h, W0, as0, ad0);
    k_gat<0><<<ROWS, DD>>>(h, bias0, h2);
    k_proj<<<ROWS/8, DD>>>(h2, W1, as1, ad1);
    k_gat<1><<<ROWS, DD>>>(nullptr, bias1, nullptr);
    k_out<<<ROWS/8, DD>>>(W_out, b_out, out);
}

// round 4
// speedup vs baseline: 1.4543x; 1.2321x over previous
#include <cuda_runtime.h>
#include <math.h>

#define BB   4
#define TT   8
#define NN   2000
#define FIN  158
#define DD   128
#define HH   4
#define CC   32
#define MAXDEG 256
#define ROWS (BB*NN)
#define ADJ_BLOCKS ROWS
#define FRONT_COMPUTE 500   // 16 rows each

// ---------------- device scratch ----------------
__device__ float  g_h  [ROWS*DD];
__device__ float  g_h2 [ROWS*DD];
__device__ float  g_xh [ROWS*DD];
__device__ float4 g_es4[ROWS];
__device__ float4 g_ed4[ROWS];
__device__ int    g_adj[ROWS*MAXDEG];
__device__ int    g_deg[ROWS];
__device__ float  g_hf [ROWS*CC];

// ============ kernel 1 (fused): adjacency build || (inproj+LN+ReLU -> proj0+att0) ============
// blocks [0, 8000): adjacency row scan (HBM-bound, launched first to start the stream)
// blocks [8000, 8500): compute, 16 rows/block, 256 thr
__global__ void k_front(const float* __restrict__ x_alpha,
                        const float* __restrict__ W_in,
                        const float* __restrict__ b_in,
                        const float* __restrict__ ln_g,
                        const float* __restrict__ ln_b,
                        const float* __restrict__ sg,
                        const float* __restrict__ W0,
                        const float* __restrict__ as0,
                        const float* __restrict__ ad0)
{
    int tid = threadIdx.x;
    if (blockIdx.x < ADJ_BLOCKS) {
        int row = blockIdx.x;                 // b*NN + i
        int i = row % NN;
        __shared__ int cnt;
        if (tid == 0) cnt = 0;
        __syncthreads();
        const float4* rp = (const float4*)(sg + (size_t)row*NN);
        for (int t = tid; t < NN/4; t += 256) {
            float4 v = rp[t];
            int j0 = 4*t;
            if (v.x > 0.f || j0   == i) { int k = atomicAdd(&cnt,1); if (k < MAXDEG) g_adj[row*MAXDEG+k] = j0;   }
            if (v.y > 0.f || j0+1 == i) { int k = atomicAdd(&cnt,1); if (k < MAXDEG) g_adj[row*MAXDEG+k] = j0+1; }
            if (v.z > 0.f || j0+2 == i) { int k = atomicAdd(&cnt,1); if (k < MAXDEG) g_adj[row*MAXDEG+k] = j0+2; }
            if (v.w > 0.f || j0+3 == i) { int k = atomicAdd(&cnt,1); if (k < MAXDEG) g_adj[row*MAXDEG+k] = j0+3; }
        }
        __syncthreads();
        if (tid == 0) g_deg[row] = cnt < MAXDEG ? cnt : MAXDEG;
        return;
    }

    // ---- compute blocks ----
    __shared__ float xr[16][FIN];
    __shared__ __align__(16) float sh[16][DD];
    int row0 = (blockIdx.x - ADJ_BLOCKS) * 16;
    {
        int b = row0 / NN;                    // 16 | NN blocks never straddle a batch
        const float* xp = x_alpha + (((size_t)b*TT + (TT-1))*NN + (row0 - b*NN))*FIN;
        for (int idx = tid; idx < 16*FIN; idx += 256)
            xr[idx/FIN][idx%FIN] = xp[idx];
    }
    __syncthreads();

    int w = tid >> 5, lane = tid & 31;
    int r0 = 2*w, r1 = 2*w + 1;
    const float* wp = W_in + 4*lane;

    // phase A: h = relu(LN(x@W_in + b_in))
    float4 bi = *(const float4*)(b_in + 4*lane);
    float4 a0 = bi, a1 = bi;
    {
        float4 wv = *(const float4*)wp;
        #pragma unroll 4
        for (int k = 0; k < FIN-1; ++k) {
            float4 wn = *(const float4*)(wp + (size_t)(k+1)*DD);
            float x0 = xr[r0][k], x1 = xr[r1][k];
            a0.x = fmaf(x0, wv.x, a0.x); a0.y = fmaf(x0, wv.y, a0.y);
            a0.z = fmaf(x0, wv.z, a0.z); a0.w = fmaf(x0, wv.w, a0.w);
            a1.x = fmaf(x1, wv.x, a1.x); a1.y = fmaf(x1, wv.y, a1.y);
            a1.z = fmaf(x1, wv.z, a1.z); a1.w = fmaf(x1, wv.w, a1.w);
            wv = wn;
        }
        float x0 = xr[r0][FIN-1], x1 = xr[r1][FIN-1];
        a0.x = fmaf(x0, wv.x, a0.x); a0.y = fmaf(x0, wv.y, a0.y);
        a0.z = fmaf(x0, wv.z, a0.z); a0.w = fmaf(x0, wv.w, a0.w);
        a1.x = fmaf(x1, wv.x, a1.x); a1.y = fmaf(x1, wv.y, a1.y);
        a1.z = fmaf(x1, wv.z, a1.z); a1.w = fmaf(x1, wv.w, a1.w);
    }
    float4 gg = *(const float4*)(ln_g + 4*lane);
    float4 gb = *(const float4*)(ln_b + 4*lane);
    {
        float s = a0.x + a0.y + a0.z + a0.w;
        for (int o = 16; o; o >>= 1) s += __shfl_xor_sync(0xffffffffu, s, o);
        float mean = s * (1.0f/DD);
        float dx=a0.x-mean, dy=a0.y-mean, dz=a0.z-mean, dw=a0.w-mean;
        float q = dx*dx + dy*dy + dz*dz + dw*dw;
        for (int o = 16; o; o >>= 1) q += __shfl_xor_sync(0xffffffffu, q, o);
        float sc = rsqrtf(q * (1.0f/DD) + 1e-5f);
        float4 y;
        y.x = fmaxf(dx*sc*gg.x + gb.x, 0.f); y.y = fmaxf(dy*sc*gg.y + gb.y, 0.f);
        y.z = fmaxf(dz*sc*gg.z + gb.z, 0.f); y.w = fmaxf(dw*sc*gg.w + gb.w, 0.f);
        *(float4*)(g_h + (size_t)(row0+r0)*DD + 4*lane) = y;
        *(float4*)(&sh[r0][4*lane]) = y;
    }
    {
        float s = a1.x + a1.y + a1.z + a1.w;
        for (int o = 16; o; o >>= 1) s += __shfl_xor_sync(0xffffffffu, s, o);
        float mean = s * (1.0f/DD);
        float dx=a1.x-mean, dy=a1.y-mean, dz=a1.z-mean, dw=a1.w-mean;
        float q = dx*dx + dy*dy + dz*dz + dw*dw;
        for (int o = 16; o; o >>= 1) q += __shfl_xor_sync(0xffffffffu, q, o);
        float sc = rsqrtf(q * (1.0f/DD) + 1e-5f);
        float4 y;
        y.x = fmaxf(dx*sc*gg.x + gb.x, 0.f); y.y = fmaxf(dy*sc*gg.y + gb.y, 0.f);
        y.z = fmaxf(dz*sc*gg.z + gb.z, 0.f); y.w = fmaxf(dw*sc*gg.w + gb.w, 0.f);
        *(float4*)(g_h + (size_t)(row0+r1)*DD + 4*lane) = y;
        *(float4*)(&sh[r1][4*lane]) = y;
    }
    __syncthreads();

    // phase B: xh0 = h@W0 ; e_src/e_dst head-dots
    const float* wp0 = W0 + 4*lane;
    float4 c0 = {0,0,0,0}, c1 = {0,0,0,0};
    {
        float4 wv = *(const float4*)wp0;
        #pragma unroll 4
        for (int k = 0; k < DD-1; ++k) {
            float4 wn = *(const float4*)(wp0 + (size_t)(k+1)*DD);
            float x0 = sh[r0][k], x1 = sh[r1][k];
            c0.x = fmaf(x0, wv.x, c0.x); c0.y = fmaf(x0, wv.y, c0.y);
            c0.z = fmaf(x0, wv.z, c0.z); c0.w = fmaf(x0, wv.w, c0.w);
            c1.x = fmaf(x1, wv.x, c1.x); c1.y = fmaf(x1, wv.y, c1.y);
            c1.z = fmaf(x1, wv.z, c1.z); c1.w = fmaf(x1, wv.w, c1.w);
            wv = wn;
        }
        float x0 = sh[r0][DD-1], x1 = sh[r1][DD-1];
        c0.x = fmaf(x0, wv.x, c0.x); c0.y = fmaf(x0, wv.y, c0.y);
        c0.z = fmaf(x0, wv.z, c0.z); c0.w = fmaf(x0, wv.w, c0.w);
        c1.x = fmaf(x1, wv.x, c1.x); c1.y = fmaf(x1, wv.y, c1.y);
        c1.z = fmaf(x1, wv.z, c1.z); c1.w = fmaf(x1, wv.w, c1.w);
    }
    *(float4*)(g_xh + (size_t)(row0+r0)*DD + 4*lane) = c0;
    *(float4*)(g_xh + (size_t)(row0+r1)*DD + 4*lane) = c1;

    float4 av = *(const float4*)(as0 + 4*lane);
    float4 dv = *(const float4*)(ad0 + 4*lane);
    float es0 = c0.x*av.x + c0.y*av.y + c0.z*av.z + c0.w*av.w;
    float ed0 = c0.x*dv.x + c0.y*dv.y + c0.z*dv.z + c0.w*dv.w;
    float es1 = c1.x*av.x + c1.y*av.y + c1.z*av.z + c1.w*av.w;
    float ed1 = c1.x*dv.x + c1.y*dv.y + c1.z*dv.z + c1.w*dv.w;
    for (int o = 4; o; o >>= 1) {
        es0 += __shfl_xor_sync(0xffffffffu, es0, o);
        ed0 += __shfl_xor_sync(0xffffffffu, ed0, o);
        es1 += __shfl_xor_sync(0xffffffffu, es1, o);
        ed1 += __shfl_xor_sync(0xffffffffu, ed1, o);
    }
    if ((lane & 7) == 0) {
        int h = lane >> 3;
        ((float*)(g_es4 + row0 + r0))[h] = es0;
        ((float*)(g_ed4 + row0 + r0))[h] = ed0;
        ((float*)(g_es4 + row0 + r1))[h] = es1;
        ((float*)(g_ed4 + row0 + r1))[h] = ed1;
    }
}

// ============ k_proj (layer 1): xh = h2@W1 ; e_src/e_dst ============
// 256 thr, 32 rows/block, warp -> 4 rows, thread -> 4 cols, W prefetch
__global__ void k_proj(const float* __restrict__ hin,
                       const float* __restrict__ W,
                       const float* __restrict__ as_,
                       const float* __restrict__ ad_)
{
    __shared__ __align__(16) float hr[32][DD];
    int row0 = blockIdx.x * 32, tid = threadIdx.x;
    {
        const float4* src = (const float4*)(hin + (size_t)row0*DD);
        float4* dst = (float4*)&hr[0][0];
        #pragma unroll
        for (int i = 0; i < 4; ++i) dst[tid + 256*i] = src[tid + 256*i];
    }
    __syncthreads();

    int w = tid >> 5, lane = tid & 31;
    int r = 4*w;
    const float* wp = W + 4*lane;
    float4 a0={0,0,0,0}, a1=a0, a2=a0, a3=a0;
    float4 wv = *(const float4*)wp;
    #pragma unroll 4
    for (int k = 0; k < DD-1; ++k) {
        float4 wn = *(const float4*)(wp + (size_t)(k+1)*DD);
        float x0=hr[r][k], x1=hr[r+1][k], x2=hr[r+2][k], x3=hr[r+3][k];
        a0.x=fmaf(x0,wv.x,a0.x); a0.y=fmaf(x0,wv.y,a0.y); a0.z=fmaf(x0,wv.z,a0.z); a0.w=fmaf(x0,wv.w,a0.w);
        a1.x=fmaf(x1,wv.x,a1.x); a1.y=fmaf(x1,wv.y,a1.y); a1.z=fmaf(x1,wv.z,a1.z); a1.w=fmaf(x1,wv.w,a1.w);
        a2.x=fmaf(x2,wv.x,a2.x); a2.y=fmaf(x2,wv.y,a2.y); a2.z=fmaf(x2,wv.z,a2.z); a2.w=fmaf(x2,wv.w,a2.w);
        a3.x=fmaf(x3,wv.x,a3.x); a3.y=fmaf(x3,wv.y,a3.y); a3.z=fmaf(x3,wv.z,a3.z); a3.w=fmaf(x3,wv.w,a3.w);
        wv = wn;
    }
    {
        int k = DD-1;
        float x0=hr[r][k], x1=hr[r+1][k], x2=hr[r+2][k], x3=hr[r+3][k];
        a0.x=fmaf(x0,wv.x,a0.x); a0.y=fmaf(x0,wv.y,a0.y); a0.z=fmaf(x0,wv.z,a0.z); a0.w=fmaf(x0,wv.w,a0.w);
        a1.x=fmaf(x1,wv.x,a1.x); a1.y=fmaf(x1,wv.y,a1.y); a1.z=fmaf(x1,wv.z,a1.z); a1.w=fmaf(x1,wv.w,a1.w);
        a2.x=fmaf(x2,wv.x,a2.x); a2.y=fmaf(x2,wv.y,a2.y); a2.z=fmaf(x2,wv.z,a2.z); a2.w=fmaf(x2,wv.w,a2.w);
        a3.x=fmaf(x3,wv.x,a3.x); a3.y=fmaf(x3,wv.y,a3.y); a3.z=fmaf(x3,wv.z,a3.z); a3.w=fmaf(x3,wv.w,a3.w);
    }
    *(float4*)(g_xh + (size_t)(row0+r  )*DD + 4*lane) = a0;
    *(float4*)(g_xh + (size_t)(row0+r+1)*DD + 4*lane) = a1;
    *(float4*)(g_xh + (size_t)(row0+r+2)*DD + 4*lane) = a2;
    *(float4*)(g_xh + (size_t)(row0+r+3)*DD + 4*lane) = a3;

    float4 av = *(const float4*)(as_ + 4*lane);
    float4 dv = *(const float4*)(ad_ + 4*lane);
    float es[4], ed[4];
    es[0]=a0.x*av.x+a0.y*av.y+a0.z*av.z+a0.w*av.w; ed[0]=a0.x*dv.x+a0.y*dv.y+a0.z*dv.z+a0.w*dv.w;
    es[1]=a1.x*av.x+a1.y*av.y+a1.z*av.z+a1.w*av.w; ed[1]=a1.x*dv.x+a1.y*dv.y+a1.z*dv.z+a1.w*dv.w;
    es[2]=a2.x*av.x+a2.y*av.y+a2.z*av.z+a2.w*av.w; ed[2]=a2.x*dv.x+a2.y*dv.y+a2.z*dv.z+a2.w*dv.w;
    es[3]=a3.x*av.x+a3.y*av.y+a3.z*av.z+a3.w*av.w; ed[3]=a3.x*dv.x+a3.y*dv.y+a3.z*dv.z+a3.w*dv.w;
    #pragma unroll
    for (int i = 0; i < 4; ++i)
        for (int o = 4; o; o >>= 1) {
            es[i] += __shfl_xor_sync(0xffffffffu, es[i], o);
            ed[i] += __shfl_xor_sync(0xffffffffu, ed[i], o);
        }
    if ((lane & 7) == 0) {
        int h = lane >> 3;
        #pragma unroll
        for (int i = 0; i < 4; ++i) {
            ((float*)(g_es4 + row0 + r + i))[h] = es[i];
            ((float*)(g_ed4 + row0 + r + i))[h] = ed[i];
        }
    }
}

// ============ k_gat: sparse softmax + float4 gather-aggregate ============
// MODE 0: hout = hin + elu(agg + bias[128])   (layer 0)
// MODE 1: g_hf = head-mean(agg) + bias[32]    (layer 1)
template <int MODE>
__global__ void k_gat(const float* __restrict__ hin,
                      const float* __restrict__ bias,
                      float* __restrict__ hout)
{
    int row = blockIdx.x;
    int b = row / NN;
    int tid = threadIdx.x, w = tid >> 5, lane = tid & 31;

    __shared__ int   sdeg;
    __shared__ int   soff[MAXDEG];
    __shared__ __align__(16) float salp[MAXDEG*HH];    // exp(lrelu(score))
    __shared__ float sinv[HH];
    __shared__ __align__(16) float spart[4][DD];

    if (tid == 0) sdeg = g_deg[row];
    __syncthreads();
    int deg = sdeg;
    int bN = b * NN;
    float4 edv = g_ed4[row];

    // scores -> exp directly (softmax is shift-invariant; no max pass)
    for (int k = tid; k < deg; k += 128) {
        int j = g_adj[row*MAXDEG + k];
        soff[k] = (bN + j) * DD;
        float4 es = g_es4[bN + j];
        float4 s;
        s.x = edv.x + es.x; s.x = s.x >= 0.f ? s.x : 0.2f*s.x;
        s.y = edv.y + es.y; s.y = s.y >= 0.f ? s.y : 0.2f*s.y;
        s.z = edv.z + es.z; s.z = s.z >= 0.f ? s.z : 0.2f*s.z;
        s.w = edv.w + es.w; s.w = s.w >= 0.f ? s.w : 0.2f*s.w;
        s.x = expf(s.x); s.y = expf(s.y); s.z = expf(s.z); s.w = expf(s.w);
        *(float4*)(salp + k*HH) = s;
    }
    __syncthreads();

    // per-head sum: warp w owns head w
    {
        float sum = 0.f;
        for (int k = lane; k < deg; k += 32) sum += salp[k*HH + w];
        for (int o = 16; o; o >>= 1) sum += __shfl_xor_sync(0xffffffffu, sum, o);
        if (lane == 0) sinv[w] = 1.0f / sum;
    }
    __syncthreads();

    // gather: warp w handles neighbors k = w, w+4, ...; 2 loads in flight
    const float* base = g_xh + 4*lane;
    int hsel = lane >> 3;
    float4 acc0 = {0,0,0,0}, acc1 = {0,0,0,0};
    int k = w;
    for (; k + 4 < deg; k += 8) {
        float a0 = salp[k*HH + hsel];
        float4 v0 = *(const float4*)(base + soff[k]);
        float a1 = salp[(k+4)*HH + hsel];
        float4 v1 = *(const float4*)(base + soff[k+4]);
        acc0.x = fmaf(a0, v0.x, acc0.x); acc0.y = fmaf(a0, v0.y, acc0.y);
        acc0.z = fmaf(a0, v0.z, acc0.z); acc0.w = fmaf(a0, v0.w, acc0.w);
        acc1.x = fmaf(a1, v1.x, acc1.x); acc1.y = fmaf(a1, v1.y, acc1.y);
        acc1.z = fmaf(a1, v1.z, acc1.z); acc1.w = fmaf(a1, v1.w, acc1.w);
    }
    if (k < deg) {
        float a0 = salp[k*HH + hsel];
        float4 v0 = *(const float4*)(base + soff[k]);
        acc0.x = fmaf(a0, v0.x, acc0.x); acc0.y = fmaf(a0, v0.y, acc0.y);
        acc0.z = fmaf(a0, v0.z, acc0.z); acc0.w = fmaf(a0, v0.w, acc0.w);
    }
    acc0.x += acc1.x; acc0.y += acc1.y; acc0.z += acc1.z; acc0.w += acc1.w;
    *(float4*)(&spart[w][4*lane]) = acc0;
    __syncthreads();

    float v = spart[0][tid] + spart[1][tid] + spart[2][tid] + spart[3][tid];
    v *= sinv[tid >> 5];

    if (MODE == 0) {
        float o0 = v + bias[tid];
        float e = o0 > 0.f ? o0 : (expf(o0) - 1.0f);     // ELU(alpha=1)
        hout[(size_t)row*DD + tid] = hin[(size_t)row*DD + tid] + e;
    } else {
        spart[0][tid] = v;
        __syncthreads();
        if (tid < CC) {
            float m4 = 0.25f * (spart[0][tid] + spart[0][32+tid] + spart[0][64+tid] + spart[0][96+tid]);
            g_hf[(size_t)row*CC + tid] = m4 + bias[tid];
        }
    }
}

// ============ k_out: out = hf @ W_out + b_out ============
__global__ void k_out(const float* __restrict__ Wout,
                      const float* __restrict__ bout,
                      float* __restrict__ out)
{
    __shared__ float hr[8*CC];
    int row0 = blockIdx.x * 8, tid = threadIdx.x;
    for (int idx = tid; idx < 8*CC; idx += 128) hr[idx] = g_hf[(size_t)row0*CC + idx];
    __syncthreads();

    int w = tid >> 5, lane = tid & 31;
    int r0 = 2*w, r1 = 2*w + 1;
    float4 bo = *(const float4*)(bout + 4*lane);
    float4 a0 = bo, a1 = bo;
    #pragma unroll
    for (int k = 0; k < CC; ++k) {
        float4 wv = *(const float4*)(Wout + k*DD + 4*lane);
        float x0 = hr[r0*CC + k], x1 = hr[r1*CC + k];
        a0.x = fmaf(x0, wv.x, a0.x); a0.y = fmaf(x0, wv.y, a0.y);
        a0.z = fmaf(x0, wv.z, a0.z); a0.w = fmaf(x0, wv.w, a0.w);
        a1.x = fmaf(x1, wv.x, a1.x); a1.y = fmaf(x1, wv.y, a1.y);
        a1.z = fmaf(x1, wv.z, a1.z); a1.w = fmaf(x1, wv.w, a1.w);
    }
    *(float4*)(out + (size_t)(row0+r0)*DD + 4*lane) = a0;
    *(float4*)(out + (size_t)(row0+r1)*DD + 4*lane) = a1;
}

// ---------------- launch ----------------
extern "C" void kernel_launch(void* const* d_in, const int* in_sizes, int n_in,
                              void* d_out, int out_size)
{
    const float* x_alpha = (const float*)d_in[0];
    const float* sg      = (const float*)d_in[1];
    const float* W_in    = (const float*)d_in[2];
    const float* b_in    = (const float*)d_in[3];
    const float* ln_g    = (const float*)d_in[4];
    const float* ln_b    = (const float*)d_in[5];
    const float* W0      = (const float*)d_in[6];
    const float* as0     = (const float*)d_in[7];
    const float* ad0     = (const float*)d_in[8];
    const float* bias0   = (const float*)d_in[9];
    const float* W1      = (const float*)d_in[10];
    const float* as1     = (const float*)d_in[11];
    const float* ad1     = (const float*)d_in[12];
    const float* bias1   = (const float*)d_in[13];
    const float* W_out   = (const float*)d_in[14];
    const float* b_out   = (const float*)d_in[15];
    float* out = (float*)d_out;

    float *h, *h2;
    cudaGetSymbolAddress((void**)&h,  g_h);
    cudaGetSymbolAddress((void**)&h2, g_h2);

    k_front<<<ADJ_BLOCKS + FRONT_COMPUTE, 256>>>(x_alpha, W_in, b_in, ln_g, ln_b,
                                                 sg, W0, as0, ad0);
    k_gat<0><<<ROWS, DD>>>(h, bias0, h2);
    k_proj<<<ROWS/32, 256>>>(h2, W1, as1, ad1);
    k_gat<1><<<ROWS, DD>>>(nullptr, bias1, nullptr);
    k_out<<<ROWS/8, DD>>>(W_out, b_out, out);
}

// round 5
// speedup vs baseline: 1.6408x; 1.1283x over previous
#include <cuda_runtime.h>
#include <math.h>

#define BB   4
#define TT   8
#define NN   2000
#define FIN  158
#define DD   128
#define HH   4
#define CC   32
#define MAXDEG 256
#define ROWS (BB*NN)
#define FRONT_COMPUTE 500            // 16 rows each
#define ADJ_BLOCKS (ROWS/4)          // 4 rows each

// ---------------- device scratch ----------------
__device__ float  g_h  [ROWS*DD];
__device__ float  g_h2 [ROWS*DD];
__device__ float  g_xh [ROWS*DD];
__device__ float4 g_es4[ROWS];
__device__ float4 g_ed4[ROWS];
__device__ int    g_adj[ROWS*MAXDEG];
__device__ int    g_deg[ROWS];

// ============ kernel 1 (fused): (inproj+LN+ReLU -> proj0+att0) || adjacency build ============
// blocks [0, 500): compute, 16 rows/block, 256 thr
// blocks [500, 500+2000): adjacency scan, 4 rows/block
__global__ void k_front(const float* __restrict__ x_alpha,
                        const float* __restrict__ W_in,
                        const float* __restrict__ b_in,
                        const float* __restrict__ ln_g,
                        const float* __restrict__ ln_b,
                        const float* __restrict__ sg,
                        const float* __restrict__ W0,
                        const float* __restrict__ as0,
                        const float* __restrict__ ad0)
{
    int tid = threadIdx.x;
    if (blockIdx.x >= FRONT_COMPUTE) {
        // ---- adjacency: 4 rows, 64 threads each ----
        int base = (blockIdx.x - FRONT_COMPUTE) * 4;
        int sub = tid >> 6, c = tid & 63;
        int row = base + sub;
        int i = row % NN;
        __shared__ int cnt[4];
        if (tid < 4) cnt[tid] = 0;
        __syncthreads();
        const float4* rp = (const float4*)(sg + (size_t)row*NN);
        #pragma unroll 2
        for (int t = c; t < NN/4; t += 64) {
            float4 v = rp[t];
            int j0 = 4*t;
            if (v.x > 0.f || j0   == i) { int k = atomicAdd(&cnt[sub],1); if (k < MAXDEG) g_adj[row*MAXDEG+k] = j0;   }
            if (v.y > 0.f || j0+1 == i) { int k = atomicAdd(&cnt[sub],1); if (k < MAXDEG) g_adj[row*MAXDEG+k] = j0+1; }
            if (v.z > 0.f || j0+2 == i) { int k = atomicAdd(&cnt[sub],1); if (k < MAXDEG) g_adj[row*MAXDEG+k] = j0+2; }
            if (v.w > 0.f || j0+3 == i) { int k = atomicAdd(&cnt[sub],1); if (k < MAXDEG) g_adj[row*MAXDEG+k] = j0+3; }
        }
        __syncthreads();
        if (c == 0) g_deg[row] = cnt[sub] < MAXDEG ? cnt[sub] : MAXDEG;
        return;
    }

    // ---- compute blocks ----
    __shared__ float xr[16][FIN];
    __shared__ __align__(16) float sh[16][DD];
    int row0 = blockIdx.x * 16;
    {
        int b = row0 / NN;                    // 16 | NN: blocks never straddle a batch
        const float* xp = x_alpha + (((size_t)b*TT + (TT-1))*NN + (row0 - b*NN))*FIN;
        for (int idx = tid; idx < 16*FIN; idx += 256)
            xr[idx/FIN][idx%FIN] = xp[idx];
    }
    __syncthreads();

    int w = tid >> 5, lane = tid & 31;
    int r0 = 2*w, r1 = 2*w + 1;
    const float* wp = W_in + 4*lane;

    // phase A: h = relu(LN(x@W_in + b_in))
    float4 bi = *(const float4*)(b_in + 4*lane);
    float4 a0 = bi, a1 = bi;
    {
        float4 wv = *(const float4*)wp;
        #pragma unroll 4
        for (int k = 0; k < FIN-1; ++k) {
            float4 wn = *(const float4*)(wp + (size_t)(k+1)*DD);
            float x0 = xr[r0][k], x1 = xr[r1][k];
            a0.x = fmaf(x0, wv.x, a0.x); a0.y = fmaf(x0, wv.y, a0.y);
            a0.z = fmaf(x0, wv.z, a0.z); a0.w = fmaf(x0, wv.w, a0.w);
            a1.x = fmaf(x1, wv.x, a1.x); a1.y = fmaf(x1, wv.y, a1.y);
            a1.z = fmaf(x1, wv.z, a1.z); a1.w = fmaf(x1, wv.w, a1.w);
            wv = wn;
        }
        float x0 = xr[r0][FIN-1], x1 = xr[r1][FIN-1];
        a0.x = fmaf(x0, wv.x, a0.x); a0.y = fmaf(x0, wv.y, a0.y);
        a0.z = fmaf(x0, wv.z, a0.z); a0.w = fmaf(x0, wv.w, a0.w);
        a1.x = fmaf(x1, wv.x, a1.x); a1.y = fmaf(x1, wv.y, a1.y);
        a1.z = fmaf(x1, wv.z, a1.z); a1.w = fmaf(x1, wv.w, a1.w);
    }
    float4 gg = *(const float4*)(ln_g + 4*lane);
    float4 gb = *(const float4*)(ln_b + 4*lane);
    {
        float s = a0.x + a0.y + a0.z + a0.w;
        for (int o = 16; o; o >>= 1) s += __shfl_xor_sync(0xffffffffu, s, o);
        float mean = s * (1.0f/DD);
        float dx=a0.x-mean, dy=a0.y-mean, dz=a0.z-mean, dw=a0.w-mean;
        float q = dx*dx + dy*dy + dz*dz + dw*dw;
        for (int o = 16; o; o >>= 1) q += __shfl_xor_sync(0xffffffffu, q, o);
        float sc = rsqrtf(q * (1.0f/DD) + 1e-5f);
        float4 y;
        y.x = fmaxf(dx*sc*gg.x + gb.x, 0.f); y.y = fmaxf(dy*sc*gg.y + gb.y, 0.f);
        y.z = fmaxf(dz*sc*gg.z + gb.z, 0.f); y.w = fmaxf(dw*sc*gg.w + gb.w, 0.f);
        *(float4*)(g_h + (size_t)(row0+r0)*DD + 4*lane) = y;
        *(float4*)(&sh[r0][4*lane]) = y;
    }
    {
        float s = a1.x + a1.y + a1.z + a1.w;
        for (int o = 16; o; o >>= 1) s += __shfl_xor_sync(0xffffffffu, s, o);
        float mean = s * (1.0f/DD);
        float dx=a1.x-mean, dy=a1.y-mean, dz=a1.z-mean, dw=a1.w-mean;
        float q = dx*dx + dy*dy + dz*dz + dw*dw;
        for (int o = 16; o; o >>= 1) q += __shfl_xor_sync(0xffffffffu, q, o);
        float sc = rsqrtf(q * (1.0f/DD) + 1e-5f);
        float4 y;
        y.x = fmaxf(dx*sc*gg.x + gb.x, 0.f); y.y = fmaxf(dy*sc*gg.y + gb.y, 0.f);
        y.z = fmaxf(dz*sc*gg.z + gb.z, 0.f); y.w = fmaxf(dw*sc*gg.w + gb.w, 0.f);
        *(float4*)(g_h + (size_t)(row0+r1)*DD + 4*lane) = y;
        *(float4*)(&sh[r1][4*lane]) = y;
    }
    __syncthreads();

    // phase B: xh0 = h@W0 ; e_src/e_dst head-dots
    const float* wp0 = W0 + 4*lane;
    float4 c0 = {0,0,0,0}, c1 = {0,0,0,0};
    {
        float4 wv = *(const float4*)wp0;
        #pragma unroll 4
        for (int k = 0; k < DD-1; ++k) {
            float4 wn = *(const float4*)(wp0 + (size_t)(k+1)*DD);
            float x0 = sh[r0][k], x1 = sh[r1][k];
            c0.x = fmaf(x0, wv.x, c0.x); c0.y = fmaf(x0, wv.y, c0.y);
            c0.z = fmaf(x0, wv.z, c0.z); c0.w = fmaf(x0, wv.w, c0.w);
            c1.x = fmaf(x1, wv.x, c1.x); c1.y = fmaf(x1, wv.y, c1.y);
            c1.z = fmaf(x1, wv.z, c1.z); c1.w = fmaf(x1, wv.w, c1.w);
            wv = wn;
        }
        float x0 = sh[r0][DD-1], x1 = sh[r1][DD-1];
        c0.x = fmaf(x0, wv.x, c0.x); c0.y = fmaf(x0, wv.y, c0.y);
        c0.z = fmaf(x0, wv.z, c0.z); c0.w = fmaf(x0, wv.w, c0.w);
        c1.x = fmaf(x1, wv.x, c1.x); c1.y = fmaf(x1, wv.y, c1.y);
        c1.z = fmaf(x1, wv.z, c1.z); c1.w = fmaf(x1, wv.w, c1.w);
    }
    *(float4*)(g_xh + (size_t)(row0+r0)*DD + 4*lane) = c0;
    *(float4*)(g_xh + (size_t)(row0+r1)*DD + 4*lane) = c1;

    float4 av = *(const float4*)(as0 + 4*lane);
    float4 dv = *(const float4*)(ad0 + 4*lane);
    float es0 = c0.x*av.x + c0.y*av.y + c0.z*av.z + c0.w*av.w;
    float ed0 = c0.x*dv.x + c0.y*dv.y + c0.z*dv.z + c0.w*dv.w;
    float es1 = c1.x*av.x + c1.y*av.y + c1.z*av.z + c1.w*av.w;
    float ed1 = c1.x*dv.x + c1.y*dv.y + c1.z*dv.z + c1.w*dv.w;
    for (int o = 4; o; o >>= 1) {
        es0 += __shfl_xor_sync(0xffffffffu, es0, o);
        ed0 += __shfl_xor_sync(0xffffffffu, ed0, o);
        es1 += __shfl_xor_sync(0xffffffffu, es1, o);
        ed1 += __shfl_xor_sync(0xffffffffu, ed1, o);
    }
    if ((lane & 7) == 0) {
        int h = lane >> 3;
        ((float*)(g_es4 + row0 + r0))[h] = es0;
        ((float*)(g_ed4 + row0 + r0))[h] = ed0;
        ((float*)(g_es4 + row0 + r1))[h] = es1;
        ((float*)(g_ed4 + row0 + r1))[h] = ed1;
    }
}

// ============ k_proj (layer 1): xh = h2@W1 ; e_src/e_dst ============
__global__ void k_proj(const float* __restrict__ hin,
                       const float* __restrict__ W,
                       const float* __restrict__ as_,
                       const float* __restrict__ ad_)
{
    __shared__ __align__(16) float hr[32][DD];
    int row0 = blockIdx.x * 32, tid = threadIdx.x;
    {
        const float4* src = (const float4*)(hin + (size_t)row0*DD);
        float4* dst = (float4*)&hr[0][0];
        #pragma unroll
        for (int i = 0; i < 4; ++i) dst[tid + 256*i] = src[tid + 256*i];
    }
    __syncthreads();

    int w = tid >> 5, lane = tid & 31;
    int r = 4*w;
    const float* wp = W + 4*lane;
    float4 a0={0,0,0,0}, a1=a0, a2=a0, a3=a0;
    float4 wv = *(const float4*)wp;
    #pragma unroll 4
    for (int k = 0; k < DD-1; ++k) {
        float4 wn = *(const float4*)(wp + (size_t)(k+1)*DD);
        float x0=hr[r][k], x1=hr[r+1][k], x2=hr[r+2][k], x3=hr[r+3][k];
        a0.x=fmaf(x0,wv.x,a0.x); a0.y=fmaf(x0,wv.y,a0.y); a0.z=fmaf(x0,wv.z,a0.z); a0.w=fmaf(x0,wv.w,a0.w);
        a1.x=fmaf(x1,wv.x,a1.x); a1.y=fmaf(x1,wv.y,a1.y); a1.z=fmaf(x1,wv.z,a1.z); a1.w=fmaf(x1,wv.w,a1.w);
        a2.x=fmaf(x2,wv.x,a2.x); a2.y=fmaf(x2,wv.y,a2.y); a2.z=fmaf(x2,wv.z,a2.z); a2.w=fmaf(x2,wv.w,a2.w);
        a3.x=fmaf(x3,wv.x,a3.x); a3.y=fmaf(x3,wv.y,a3.y); a3.z=fmaf(x3,wv.z,a3.z); a3.w=fmaf(x3,wv.w,a3.w);
        wv = wn;
    }
    {
        int k = DD-1;
        float x0=hr[r][k], x1=hr[r+1][k], x2=hr[r+2][k], x3=hr[r+3][k];
        a0.x=fmaf(x0,wv.x,a0.x); a0.y=fmaf(x0,wv.y,a0.y); a0.z=fmaf(x0,wv.z,a0.z); a0.w=fmaf(x0,wv.w,a0.w);
        a1.x=fmaf(x1,wv.x,a1.x); a1.y=fmaf(x1,wv.y,a1.y); a1.z=fmaf(x1,wv.z,a1.z); a1.w=fmaf(x1,wv.w,a1.w);
        a2.x=fmaf(x2,wv.x,a2.x); a2.y=fmaf(x2,wv.y,a2.y); a2.z=fmaf(x2,wv.z,a2.z); a2.w=fmaf(x2,wv.w,a2.w);
        a3.x=fmaf(x3,wv.x,a3.x); a3.y=fmaf(x3,wv.y,a3.y); a3.z=fmaf(x3,wv.z,a3.z); a3.w=fmaf(x3,wv.w,a3.w);
    }
    *(float4*)(g_xh + (size_t)(row0+r  )*DD + 4*lane) = a0;
    *(float4*)(g_xh + (size_t)(row0+r+1)*DD + 4*lane) = a1;
    *(float4*)(g_xh + (size_t)(row0+r+2)*DD + 4*lane) = a2;
    *(float4*)(g_xh + (size_t)(row0+r+3)*DD + 4*lane) = a3;

    float4 av = *(const float4*)(as_ + 4*lane);
    float4 dv = *(const float4*)(ad_ + 4*lane);
    float es[4], ed[4];
    es[0]=a0.x*av.x+a0.y*av.y+a0.z*av.z+a0.w*av.w; ed[0]=a0.x*dv.x+a0.y*dv.y+a0.z*dv.z+a0.w*dv.w;
    es[1]=a1.x*av.x+a1.y*av.y+a1.z*av.z+a1.w*av.w; ed[1]=a1.x*dv.x+a1.y*dv.y+a1.z*dv.z+a1.w*dv.w;
    es[2]=a2.x*av.x+a2.y*av.y+a2.z*av.z+a2.w*av.w; ed[2]=a2.x*dv.x+a2.y*dv.y+a2.z*dv.z+a2.w*dv.w;
    es[3]=a3.x*av.x+a3.y*av.y+a3.z*av.z+a3.w*av.w; ed[3]=a3.x*dv.x+a3.y*dv.y+a3.z*dv.z+a3.w*dv.w;
    #pragma unroll
    for (int i = 0; i < 4; ++i)
        for (int o = 4; o; o >>= 1) {
            es[i] += __shfl_xor_sync(0xffffffffu, es[i], o);
            ed[i] += __shfl_xor_sync(0xffffffffu, ed[i], o);
        }
    if ((lane & 7) == 0) {
        int h = lane >> 3;
        #pragma unroll
        for (int i = 0; i < 4; ++i) {
            ((float*)(g_es4 + row0 + r + i))[h] = es[i];
            ((float*)(g_ed4 + row0 + r + i))[h] = ed[i];
        }
    }
}

// ============ k_gat: 2 rows/block, sparse softmax + 4-deep gather ============
// MODE 0: hout = hin + elu(agg + bias[128])
// MODE 1: out = (head-mean(agg)+bias[32]) @ W_out + b_out   (fused final GEMM)
template <int MODE>
__global__ void k_gat(const float* __restrict__ hin,
                      const float* __restrict__ bias,
                      float* __restrict__ hout,
                      const float* __restrict__ Wout,
                      const float* __restrict__ bout,
                      float* __restrict__ out)
{
    int row0 = blockIdx.x * 2;
    int bN = (row0 / NN) * NN;                 // rows never straddle a batch (NN even)
    int tid = threadIdx.x;
    int w = tid >> 5, lane = tid & 31;
    int rsel = w >> 2;                         // which row this warp serves
    int wl = w & 3;                            // warp-within-row
    int row = row0 + rsel;

    __shared__ int   sdeg[2];
    __shared__ int   soff[2][MAXDEG];
    __shared__ __align__(16) float salp[2][MAXDEG*HH];
    __shared__ float sinv[2][HH];
    __shared__ __align__(16) float spart[2][4][DD];
    __shared__ float shf[2][CC];

    if (tid < 2) sdeg[tid] = g_deg[row0 + tid];
    __syncthreads();
    int deg = sdeg[rsel];
    float4 edv = g_ed4[row];

    // scores -> exp (softmax shift-invariance: no max pass needed)
    int t128 = tid & 127;
    for (int k = t128; k < deg; k += 128) {
        int j = g_adj[row*MAXDEG + k];
        soff[rsel][k] = (bN + j) * DD;
        float4 es = g_es4[bN + j];
        float4 s;
        s.x = edv.x + es.x; s.x = s.x >= 0.f ? s.x : 0.2f*s.x;
        s.y = edv.y + es.y; s.y = s.y >= 0.f ? s.y : 0.2f*s.y;
        s.z = edv.z + es.z; s.z = s.z >= 0.f ? s.z : 0.2f*s.z;
        s.w = edv.w + es.w; s.w = s.w >= 0.f ? s.w : 0.2f*s.w;
        s.x = expf(s.x); s.y = expf(s.y); s.z = expf(s.z); s.w = expf(s.w);
        *(float4*)(&salp[rsel][k*HH]) = s;
    }
    __syncthreads();

    // per-head sum: warp (rsel, wl) owns head wl of row rsel
    {
        float sum = 0.f;
        for (int k = lane; k < deg; k += 32) sum += salp[rsel][k*HH + wl];
        for (int o = 16; o; o >>= 1) sum += __shfl_xor_sync(0xffffffffu, sum, o);
        if (lane == 0) sinv[rsel][wl] = 1.0f / sum;
    }
    __syncthreads();

    // gather: warp takes k = wl, wl+4, ... ; 4 loads in flight
    {
        const float* base = g_xh + 4*lane;
        const int*   so = soff[rsel];
        const float* al = salp[rsel];
        int hsel = lane >> 3;
        float4 A0={0,0,0,0}, A1=A0, A2=A0, A3=A0;
        int k = wl;
        for (; k + 12 < deg; k += 16) {
            float a0 = al[ k     *HH + hsel]; float4 v0 = *(const float4*)(base + so[k]);
            float a1 = al[(k+ 4)*HH + hsel]; float4 v1 = *(const float4*)(base + so[k+ 4]);
            float a2 = al[(k+ 8)*HH + hsel]; float4 v2 = *(const float4*)(base + so[k+ 8]);
            float a3 = al[(k+12)*HH + hsel]; float4 v3 = *(const float4*)(base + so[k+12]);
            A0.x=fmaf(a0,v0.x,A0.x); A0.y=fmaf(a0,v0.y,A0.y); A0.z=fmaf(a0,v0.z,A0.z); A0.w=fmaf(a0,v0.w,A0.w);
            A1.x=fmaf(a1,v1.x,A1.x); A1.y=fmaf(a1,v1.y,A1.y); A1.z=fmaf(a1,v1.z,A1.z); A1.w=fmaf(a1,v1.w,A1.w);
            A2.x=fmaf(a2,v2.x,A2.x); A2.y=fmaf(a2,v2.y,A2.y); A2.z=fmaf(a2,v2.z,A2.z); A2.w=fmaf(a2,v2.w,A2.w);
            A3.x=fmaf(a3,v3.x,A3.x); A3.y=fmaf(a3,v3.y,A3.y); A3.z=fmaf(a3,v3.z,A3.z); A3.w=fmaf(a3,v3.w,A3.w);
        }
        for (; k < deg; k += 4) {
            float a0 = al[k*HH + hsel]; float4 v0 = *(const float4*)(base + so[k]);
            A0.x=fmaf(a0,v0.x,A0.x); A0.y=fmaf(a0,v0.y,A0.y); A0.z=fmaf(a0,v0.z,A0.z); A0.w=fmaf(a0,v0.w,A0.w);
        }
        A0.x += A1.x + A2.x + A3.x; A0.y += A1.y + A2.y + A3.y;
        A0.z += A1.z + A2.z + A3.z; A0.w += A1.w + A2.w + A3.w;
        *(float4*)(&spart[rsel][wl][4*lane]) = A0;
    }
    __syncthreads();

    // combine partials: 256 thr -> (row r, dim d)
    int r = tid >> 7, d = tid & 127;
    float v = spart[r][0][d] + spart[r][1][d] + spart[r][2][d] + spart[r][3][d];
    v *= sinv[r][d >> 5];

    if (MODE == 0) {
        float o0 = v + bias[d];
        float e = o0 > 0.f ? o0 : (expf(o0) - 1.0f);      // ELU(alpha=1)
        hout[(size_t)(row0+r)*DD + d] = hin[(size_t)(row0+r)*DD + d] + e;
    } else {
        __syncthreads();
        spart[r][0][d] = v;
        __syncthreads();
        if (tid < 2*CC) {
            int rr = tid >> 5, c = tid & 31;
            shf[rr][c] = 0.25f * (spart[rr][0][c] + spart[rr][0][32+c]
                                + spart[rr][0][64+c] + spart[rr][0][96+c]) + bias[c];
        }
        __syncthreads();
        float acc = bout[d];
        #pragma unroll
        for (int k = 0; k < CC; ++k)
            acc = fmaf(shf[r][k], Wout[k*DD + d], acc);
        out[(size_t)(row0+r)*DD + d] = acc;
    }
}

// ---------------- launch ----------------
extern "C" void kernel_launch(void* const* d_in, const int* in_sizes, int n_in,
                              void* d_out, int out_size)
{
    const float* x_alpha = (const float*)d_in[0];
    const float* sg      = (const float*)d_in[1];
    const float* W_in    = (const float*)d_in[2];
    const float* b_in    = (const float*)d_in[3];
    const float* ln_g    = (const float*)d_in[4];
    const float* ln_b    = (const float*)d_in[5];
    const float* W0      = (const float*)d_in[6];
    const float* as0     = (const float*)d_in[7];
    const float* ad0     = (const float*)d_in[8];
    const float* bias0   = (const float*)d_in[9];
    const float* W1      = (const float*)d_in[10];
    const float* as1     = (const float*)d_in[11];
    const float* ad1     = (const float*)d_in[12];
    const float* bias1   = (const float*)d_in[13];
    const float* W_out   = (const float*)d_in[14];
    const float* b_out   = (const float*)d_in[15];
    float* out = (float*)d_out;

    float *h, *h2;
    cudaGetSymbolAddress((void**)&h,  g_h);
    cudaGetSymbolAddress((void**)&h2, g_h2);

    k_front<<<FRONT_COMPUTE + ADJ_BLOCKS, 256>>>(x_alpha, W_in, b_in, ln_g, ln_b,
                                                 sg, W0, as0, ad0);
    k_gat<0><<<ROWS/2, 256>>>(h, bias0, h2, nullptr, nullptr, nullptr);
    k_proj<<<ROWS/32, 256>>>(h2, W1, as1, ad1);
    k_gat<1><<<ROWS/2, 256>>>(nullptr, bias1, nullptr, W_out, b_out, out);
}

// round 6
// speedup vs baseline: 1.7780x; 1.0836x over previous
#include <cuda_runtime.h>
#include <math.h>

#define BB   4
#define TT   8
#define NN   2000
#define FIN  158
#define DD   128
#define HH   4
#define CC   32
#define MAXDEG 256
#define SDEG 128
#define ROWS (BB*NN)
#define FRONT_COMPUTE 500            // 16 rows each
#define ADJ_BLOCKS (ROWS/4)          // 4 rows each

// ---------------- device scratch ----------------
__device__ float  g_h  [ROWS*DD];
__device__ float  g_h2 [ROWS*DD];
__device__ float  g_xh [ROWS*DD];
__device__ float4 g_es4[ROWS];
__device__ float4 g_ed4[ROWS];
__device__ int    g_adj[ROWS*MAXDEG];
__device__ int    g_deg[ROWS];

// ============ kernel 1 (fused): (inproj+LN+ReLU -> proj0+att0) || adjacency build ============
__global__ void k_front(const float* __restrict__ x_alpha,
                        const float* __restrict__ W_in,
                        const float* __restrict__ b_in,
                        const float* __restrict__ ln_g,
                        const float* __restrict__ ln_b,
                        const float* __restrict__ sg,
                        const float* __restrict__ W0,
                        const float* __restrict__ as0,
                        const float* __restrict__ ad0)
{
    int tid = threadIdx.x;
    if (blockIdx.x >= FRONT_COMPUTE) {
        // ---- adjacency: 4 rows, 64 threads each ----
        int base = (blockIdx.x - FRONT_COMPUTE) * 4;
        int sub = tid >> 6, c = tid & 63;
        int row = base + sub;
        int i = row % NN;
        __shared__ int cnt[4];
        if (tid < 4) cnt[tid] = 0;
        __syncthreads();
        const float4* rp = (const float4*)(sg + (size_t)row*NN);
        #pragma unroll 2
        for (int t = c; t < NN/4; t += 64) {
            float4 v = rp[t];
            int j0 = 4*t;
            if (v.x > 0.f || j0   == i) { int k = atomicAdd(&cnt[sub],1); if (k < MAXDEG) g_adj[row*MAXDEG+k] = j0;   }
            if (v.y > 0.f || j0+1 == i) { int k = atomicAdd(&cnt[sub],1); if (k < MAXDEG) g_adj[row*MAXDEG+k] = j0+1; }
            if (v.z > 0.f || j0+2 == i) { int k = atomicAdd(&cnt[sub],1); if (k < MAXDEG) g_adj[row*MAXDEG+k] = j0+2; }
            if (v.w > 0.f || j0+3 == i) { int k = atomicAdd(&cnt[sub],1); if (k < MAXDEG) g_adj[row*MAXDEG+k] = j0+3; }
        }
        __syncthreads();
        if (c == 0) g_deg[row] = cnt[sub] < MAXDEG ? cnt[sub] : MAXDEG;
        return;
    }

    // ---- compute blocks ----
    __shared__ float xr[16][FIN];
    __shared__ __align__(16) float sh[16][DD];
    int row0 = blockIdx.x * 16;
    {
        int b = row0 / NN;                    // 16 | NN: blocks never straddle a batch
        const float* xp = x_alpha + (((size_t)b*TT + (TT-1))*NN + (row0 - b*NN))*FIN;
        for (int idx = tid; idx < 16*FIN; idx += 256)
            xr[idx/FIN][idx%FIN] = xp[idx];
    }
    __syncthreads();

    int w = tid >> 5, lane = tid & 31;
    int r0 = 2*w, r1 = 2*w + 1;
    const float* wp = W_in + 4*lane;

    // phase A: h = relu(LN(x@W_in + b_in))
    float4 bi = *(const float4*)(b_in + 4*lane);
    float4 a0 = bi, a1 = bi;
    {
        float4 wv = *(const float4*)wp;
        #pragma unroll 4
        for (int k = 0; k < FIN-1; ++k) {
            float4 wn = *(const float4*)(wp + (size_t)(k+1)*DD);
            float x0 = xr[r0][k], x1 = xr[r1][k];
            a0.x = fmaf(x0, wv.x, a0.x); a0.y = fmaf(x0, wv.y, a0.y);
            a0.z = fmaf(x0, wv.z, a0.z); a0.w = fmaf(x0, wv.w, a0.w);
            a1.x = fmaf(x1, wv.x, a1.x); a1.y = fmaf(x1, wv.y, a1.y);
            a1.z = fmaf(x1, wv.z, a1.z); a1.w = fmaf(x1, wv.w, a1.w);
            wv = wn;
        }
        float x0 = xr[r0][FIN-1], x1 = xr[r1][FIN-1];
        a0.x = fmaf(x0, wv.x, a0.x); a0.y = fmaf(x0, wv.y, a0.y);
        a0.z = fmaf(x0, wv.z, a0.z); a0.w = fmaf(x0, wv.w, a0.w);
        a1.x = fmaf(x1, wv.x, a1.x); a1.y = fmaf(x1, wv.y, a1.y);
        a1.z = fmaf(x1, wv.z, a1.z); a1.w = fmaf(x1, wv.w, a1.w);
    }
    float4 gg = *(const float4*)(ln_g + 4*lane);
    float4 gb = *(const float4*)(ln_b + 4*lane);
    {
        float s = a0.x + a0.y + a0.z + a0.w;
        for (int o = 16; o; o >>= 1) s += __shfl_xor_sync(0xffffffffu, s, o);
        float mean = s * (1.0f/DD);
        float dx=a0.x-mean, dy=a0.y-mean, dz=a0.z-mean, dw=a0.w-mean;
        float q = dx*dx + dy*dy + dz*dz + dw*dw;
        for (int o = 16; o; o >>= 1) q += __shfl_xor_sync(0xffffffffu, q, o);
        float sc = rsqrtf(q * (1.0f/DD) + 1e-5f);
        float4 y;
        y.x = fmaxf(dx*sc*gg.x + gb.x, 0.f); y.y = fmaxf(dy*sc*gg.y + gb.y, 0.f);
        y.z = fmaxf(dz*sc*gg.z + gb.z, 0.f); y.w = fmaxf(dw*sc*gg.w + gb.w, 0.f);
        *(float4*)(g_h + (size_t)(row0+r0)*DD + 4*lane) = y;
        *(float4*)(&sh[r0][4*lane]) = y;
    }
    {
        float s = a1.x + a1.y + a1.z + a1.w;
        for (int o = 16; o; o >>= 1) s += __shfl_xor_sync(0xffffffffu, s, o);
        float mean = s * (1.0f/DD);
        float dx=a1.x-mean, dy=a1.y-mean, dz=a1.z-mean, dw=a1.w-mean;
        float q = dx*dx + dy*dy + dz*dz + dw*dw;
        for (int o = 16; o; o >>= 1) q += __shfl_xor_sync(0xffffffffu, q, o);
        float sc = rsqrtf(q * (1.0f/DD) + 1e-5f);
        float4 y;
        y.x = fmaxf(dx*sc*gg.x + gb.x, 0.f); y.y = fmaxf(dy*sc*gg.y + gb.y, 0.f);
        y.z = fmaxf(dz*sc*gg.z + gb.z, 0.f); y.w = fmaxf(dw*sc*gg.w + gb.w, 0.f);
        *(float4*)(g_h + (size_t)(row0+r1)*DD + 4*lane) = y;
        *(float4*)(&sh[r1][4*lane]) = y;
    }
    __syncthreads();

    // phase B: xh0 = h@W0 ; e_src/e_dst head-dots
    const float* wp0 = W0 + 4*lane;
    float4 c0 = {0,0,0,0}, c1 = {0,0,0,0};
    {
        float4 wv = *(const float4*)wp0;
        #pragma unroll 4
        for (int k = 0; k < DD-1; ++k) {
            float4 wn = *(const float4*)(wp0 + (size_t)(k+1)*DD);
            float x0 = sh[r0][k], x1 = sh[r1][k];
            c0.x = fmaf(x0, wv.x, c0.x); c0.y = fmaf(x0, wv.y, c0.y);
            c0.z = fmaf(x0, wv.z, c0.z); c0.w = fmaf(x0, wv.w, c0.w);
            c1.x = fmaf(x1, wv.x, c1.x); c1.y = fmaf(x1, wv.y, c1.y);
            c1.z = fmaf(x1, wv.z, c1.z); c1.w = fmaf(x1, wv.w, c1.w);
            wv = wn;
        }
        float x0 = sh[r0][DD-1], x1 = sh[r1][DD-1];
        c0.x = fmaf(x0, wv.x, c0.x); c0.y = fmaf(x0, wv.y, c0.y);
        c0.z = fmaf(x0, wv.z, c0.z); c0.w = fmaf(x0, wv.w, c0.w);
        c1.x = fmaf(x1, wv.x, c1.x); c1.y = fmaf(x1, wv.y, c1.y);
        c1.z = fmaf(x1, wv.z, c1.z); c1.w = fmaf(x1, wv.w, c1.w);
    }
    *(float4*)(g_xh + (size_t)(row0+r0)*DD + 4*lane) = c0;
    *(float4*)(g_xh + (size_t)(row0+r1)*DD + 4*lane) = c1;

    float4 av = *(const float4*)(as0 + 4*lane);
    float4 dv = *(const float4*)(ad0 + 4*lane);
    float es0 = c0.x*av.x + c0.y*av.y + c0.z*av.z + c0.w*av.w;
    float ed0 = c0.x*dv.x + c0.y*dv.y + c0.z*dv.z + c0.w*dv.w;
    float es1 = c1.x*av.x + c1.y*av.y + c1.z*av.z + c1.w*av.w;
    float ed1 = c1.x*dv.x + c1.y*dv.y + c1.z*dv.z + c1.w*dv.w;
    for (int o = 4; o; o >>= 1) {
        es0 += __shfl_xor_sync(0xffffffffu, es0, o);
        ed0 += __shfl_xor_sync(0xffffffffu, ed0, o);
        es1 += __shfl_xor_sync(0xffffffffu, es1, o);
        ed1 += __shfl_xor_sync(0xffffffffu, ed1, o);
    }
    if ((lane & 7) == 0) {
        int h = lane >> 3;
        ((float*)(g_es4 + row0 + r0))[h] = es0;
        ((float*)(g_ed4 + row0 + r0))[h] = ed0;
        ((float*)(g_es4 + row0 + r1))[h] = es1;
        ((float*)(g_ed4 + row0 + r1))[h] = ed1;
    }
}

// ============ k_proj (layer 1): xh = h2@W1 ; e_src/e_dst ============
__global__ void k_proj(const float* __restrict__ hin,
                       const float* __restrict__ W,
                       const float* __restrict__ as_,
                       const float* __restrict__ ad_)
{
    __shared__ __align__(16) float hr[32][DD];
    int row0 = blockIdx.x * 32, tid = threadIdx.x;
    {
        const float4* src = (const float4*)(hin + (size_t)row0*DD);
        float4* dst = (float4*)&hr[0][0];
        #pragma unroll
        for (int i = 0; i < 4; ++i) dst[tid + 256*i] = src[tid + 256*i];
    }
    __syncthreads();

    int w = tid >> 5, lane = tid & 31;
    int r = 4*w;
    const float* wp = W + 4*lane;
    float4 a0={0,0,0,0}, a1=a0, a2=a0, a3=a0;
    float4 wv = *(const float4*)wp;
    #pragma unroll 4
    for (int k = 0; k < DD-1; ++k) {
        float4 wn = *(const float4*)(wp + (size_t)(k+1)*DD);
        float x0=hr[r][k], x1=hr[r+1][k], x2=hr[r+2][k], x3=hr[r+3][k];
        a0.x=fmaf(x0,wv.x,a0.x); a0.y=fmaf(x0,wv.y,a0.y); a0.z=fmaf(x0,wv.z,a0.z); a0.w=fmaf(x0,wv.w,a0.w);
        a1.x=fmaf(x1,wv.x,a1.x); a1.y=fmaf(x1,wv.y,a1.y); a1.z=fmaf(x1,wv.z,a1.z); a1.w=fmaf(x1,wv.w,a1.w);
        a2.x=fmaf(x2,wv.x,a2.x); a2.y=fmaf(x2,wv.y,a2.y); a2.z=fmaf(x2,wv.z,a2.z); a2.w=fmaf(x2,wv.w,a2.w);
        a3.x=fmaf(x3,wv.x,a3.x); a3.y=fmaf(x3,wv.y,a3.y); a3.z=fmaf(x3,wv.z,a3.z); a3.w=fmaf(x3,wv.w,a3.w);
        wv = wn;
    }
    {
        int k = DD-1;
        float x0=hr[r][k], x1=hr[r+1][k], x2=hr[r+2][k], x3=hr[r+3][k];
        a0.x=fmaf(x0,wv.x,a0.x); a0.y=fmaf(x0,wv.y,a0.y); a0.z=fmaf(x0,wv.z,a0.z); a0.w=fmaf(x0,wv.w,a0.w);
        a1.x=fmaf(x1,wv.x,a1.x); a1.y=fmaf(x1,wv.y,a1.y); a1.z=fmaf(x1,wv.z,a1.z); a1.w=fmaf(x1,wv.w,a1.w);
        a2.x=fmaf(x2,wv.x,a2.x); a2.y=fmaf(x2,wv.y,a2.y); a2.z=fmaf(x2,wv.z,a2.z); a2.w=fmaf(x2,wv.w,a2.w);
        a3.x=fmaf(x3,wv.x,a3.x); a3.y=fmaf(x3,wv.y,a3.y); a3.z=fmaf(x3,wv.z,a3.z); a3.w=fmaf(x3,wv.w,a3.w);
    }
    *(float4*)(g_xh + (size_t)(row0+r  )*DD + 4*lane) = a0;
    *(float4*)(g_xh + (size_t)(row0+r+1)*DD + 4*lane) = a1;
    *(float4*)(g_xh + (size_t)(row0+r+2)*DD + 4*lane) = a2;
    *(float4*)(g_xh + (size_t)(row0+r+3)*DD + 4*lane) = a3;

    float4 av = *(const float4*)(as_ + 4*lane);
    float4 dv = *(const float4*)(ad_ + 4*lane);
    float es[4], ed[4];
    es[0]=a0.x*av.x+a0.y*av.y+a0.z*av.z+a0.w*av.w; ed[0]=a0.x*dv.x+a0.y*dv.y+a0.z*dv.z+a0.w*dv.w;
    es[1]=a1.x*av.x+a1.y*av.y+a1.z*av.z+a1.w*av.w; ed[1]=a1.x*dv.x+a1.y*dv.y+a1.z*dv.z+a1.w*dv.w;
    es[2]=a2.x*av.x+a2.y*av.y+a2.z*av.z+a2.w*av.w; ed[2]=a2.x*dv.x+a2.y*dv.y+a2.z*dv.z+a2.w*dv.w;
    es[3]=a3.x*av.x+a3.y*av.y+a3.z*av.z+a3.w*av.w; ed[3]=a3.x*dv.x+a3.y*dv.y+a3.z*dv.z+a3.w*dv.w;
    #pragma unroll
    for (int i = 0; i < 4; ++i)
        for (int o = 4; o; o >>= 1) {
            es[i] += __shfl_xor_sync(0xffffffffu, es[i], o);
            ed[i] += __shfl_xor_sync(0xffffffffu, ed[i], o);
        }
    if ((lane & 7) == 0) {
        int h = lane >> 3;
        #pragma unroll
        for (int i = 0; i < 4; ++i) {
            ((float*)(g_es4 + row0 + r + i))[h] = es[i];
            ((float*)(g_ed4 + row0 + r + i))[h] = ed[i];
        }
    }
}

// ============ k_gat: warp-per-row, no block syncs ============
// MODE 0: hout = hin + elu(agg + bias[128])
// MODE 1: out = (head-mean(agg)+bias[32]) @ W_out + b_out
template <int MODE>
__global__ void __launch_bounds__(256, 5) k_gat(
                      const float* __restrict__ hin,
                      const float* __restrict__ bias,
                      float* __restrict__ hout,
                      const float* __restrict__ Wout,
                      const float* __restrict__ bout,
                      float* __restrict__ out)
{
    int tid = threadIdx.x, w = tid >> 5, lane = tid & 31;
    int row = blockIdx.x * 8 + w;
    int bN = (row / NN) * NN;

    __shared__ int soff_s[8][SDEG];
    __shared__ __align__(16) float salp_s[8][SDEG*4];
    __shared__ __align__(16) float shf_s[8][CC];

    int deg = g_deg[row];
    if (deg > SDEG) deg = SDEG;
    float4 edv = g_ed4[row];

    // scores -> exp (softmax shift-invariance: no max pass); per-head sums
    float4 sums = {0.f, 0.f, 0.f, 0.f};
    for (int k = lane; k < deg; k += 32) {
        int j = g_adj[row*MAXDEG + k];
        soff_s[w][k] = (bN + j) * DD;
        float4 es = g_es4[bN + j];
        float4 s;
        s.x = edv.x + es.x; s.x = s.x >= 0.f ? s.x : 0.2f*s.x; s.x = expf(s.x);
        s.y = edv.y + es.y; s.y = s.y >= 0.f ? s.y : 0.2f*s.y; s.y = expf(s.y);
        s.z = edv.z + es.z; s.z = s.z >= 0.f ? s.z : 0.2f*s.z; s.z = expf(s.z);
        s.w = edv.w + es.w; s.w = s.w >= 0.f ? s.w : 0.2f*s.w; s.w = expf(s.w);
        sums.x += s.x; sums.y += s.y; sums.z += s.z; sums.w += s.w;
        *(float4*)(&salp_s[w][k*4]) = s;
    }
    for (int o = 16; o; o >>= 1) {
        sums.x += __shfl_xor_sync(0xffffffffu, sums.x, o);
        sums.y += __shfl_xor_sync(0xffffffffu, sums.y, o);
        sums.z += __shfl_xor_sync(0xffffffffu, sums.z, o);
        sums.w += __shfl_xor_sync(0xffffffffu, sums.w, o);
    }
    int hsel = lane >> 3;
    float sumh = (lane & 16) ? ((lane & 8) ? sums.w : sums.z)
                             : ((lane & 8) ? sums.y : sums.x);
    float inv = 1.0f / sumh;
    __syncwarp();

    // gather: all 32 lanes cover one 512B xh row per k; unroll 4 for MLP
    const float* base = g_xh + 4*lane;
    const int*   so = soff_s[w];
    const float* al = &salp_s[w][hsel];
    float4 A0 = {0,0,0,0}, A1 = A0;
    int k = 0;
    for (; k + 3 < deg; k += 4) {
        float a0 = al[4*k];     float4 v0 = *(const float4*)(base + so[k]);
        float a1 = al[4*k+4];   float4 v1 = *(const float4*)(base + so[k+1]);
        float a2 = al[4*k+8];   float4 v2 = *(const float4*)(base + so[k+2]);
        float a3 = al[4*k+12];  float4 v3 = *(const float4*)(base + so[k+3]);
        A0.x=fmaf(a0,v0.x,A0.x); A0.y=fmaf(a0,v0.y,A0.y); A0.z=fmaf(a0,v0.z,A0.z); A0.w=fmaf(a0,v0.w,A0.w);
        A1.x=fmaf(a1,v1.x,A1.x); A1.y=fmaf(a1,v1.y,A1.y); A1.z=fmaf(a1,v1.z,A1.z); A1.w=fmaf(a1,v1.w,A1.w);
        A0.x=fmaf(a2,v2.x,A0.x); A0.y=fmaf(a2,v2.y,A0.y); A0.z=fmaf(a2,v2.z,A0.z); A0.w=fmaf(a2,v2.w,A0.w);
        A1.x=fmaf(a3,v3.x,A1.x); A1.y=fmaf(a3,v3.y,A1.y); A1.z=fmaf(a3,v3.z,A1.z); A1.w=fmaf(a3,v3.w,A1.w);
    }
    for (; k < deg; ++k) {
        float a0 = al[4*k];     float4 v0 = *(const float4*)(base + so[k]);
        A0.x=fmaf(a0,v0.x,A0.x); A0.y=fmaf(a0,v0.y,A0.y); A0.z=fmaf(a0,v0.z,A0.z); A0.w=fmaf(a0,v0.w,A0.w);
    }
    float4 A;
    A.x = (A0.x + A1.x) * inv; A.y = (A0.y + A1.y) * inv;
    A.z = (A0.z + A1.z) * inv; A.w = (A0.w + A1.w) * inv;

    if (MODE == 0) {
        float4 bi = *(const float4*)(bias + 4*lane);
        float4 hi = *(const float4*)(hin + (size_t)row*DD + 4*lane);
        float4 y; float t;
        t = A.x + bi.x; y.x = hi.x + (t > 0.f ? t : expf(t) - 1.f);
        t = A.y + bi.y; y.y = hi.y + (t > 0.f ? t : expf(t) - 1.f);
        t = A.z + bi.z; y.z = hi.z + (t > 0.f ? t : expf(t) - 1.f);
        t = A.w + bi.w; y.w = hi.w + (t > 0.f ? t : expf(t) - 1.f);
        *(float4*)(hout + (size_t)row*DD + 4*lane) = y;
    } else {
        // head-mean via shuffles: sum over lane groups {l, l^8, l^16, l^24}
        A.x += __shfl_xor_sync(0xffffffffu, A.x, 8);  A.x += __shfl_xor_sync(0xffffffffu, A.x, 16);
        A.y += __shfl_xor_sync(0xffffffffu, A.y, 8);  A.y += __shfl_xor_sync(0xffffffffu, A.y, 16);
        A.z += __shfl_xor_sync(0xffffffffu, A.z, 8);  A.z += __shfl_xor_sync(0xffffffffu, A.z, 16);
        A.w += __shfl_xor_sync(0xffffffffu, A.w, 8);  A.w += __shfl_xor_sync(0xffffffffu, A.w, 16);
        if (lane < 8) {
            float4 bi = *(const float4*)(bias + 4*lane);
            float4 hf;
            hf.x = 0.25f*A.x + bi.x; hf.y = 0.25f*A.y + bi.y;
            hf.z = 0.25f*A.z + bi.z; hf.w = 0.25f*A.w + bi.w;
            *(float4*)(&shf_s[w][4*lane]) = hf;
        }
        __syncwarp();
        float4 acc = *(const float4*)(bout + 4*lane);
        #pragma unroll
        for (int c = 0; c < CC; ++c) {
            float x = shf_s[w][c];
            float4 wv = *(const float4*)(Wout + c*DD + 4*lane);
            acc.x = fmaf(x, wv.x, acc.x); acc.y = fmaf(x, wv.y, acc.y);
            acc.z = fmaf(x, wv.z, acc.z); acc.w = fmaf(x, wv.w, acc.w);
        }
        *(float4*)(out + (size_t)row*DD + 4*lane) = acc;
    }
}

// ---------------- launch ----------------
extern "C" void kernel_launch(void* const* d_in, const int* in_sizes, int n_in,
                              void* d_out, int out_size)
{
    const float* x_alpha = (const float*)d_in[0];
    const float* sg      = (const float*)d_in[1];
    const float* W_in    = (const float*)d_in[2];
    const float* b_in    = (const float*)d_in[3];
    const float* ln_g    = (const float*)d_in[4];
    const float* ln_b    = (const float*)d_in[5];
    const float* W0      = (const float*)d_in[6];
    const float* as0     = (const float*)d_in[7];
    const float* ad0     = (const float*)d_in[8];
    const float* bias0   = (const float*)d_in[9];
    const float* W1      = (const float*)d_in[10];
    const float* as1     = (const float*)d_in[11];
    const float* ad1     = (const float*)d_in[12];
    const float* bias1   = (const float*)d_in[13];
    const float* W_out   = (const float*)d_in[14];
    const float* b_out   = (const float*)d_in[15];
    float* out = (float*)d_out;

    float *h, *h2;
    cudaGetSymbolAddress((void**)&h,  g_h);
    cudaGetSymbolAddress((void**)&h2, g_h2);

    k_front<<<FRONT_COMPUTE + ADJ_BLOCKS, 256>>>(x_alpha, W_in, b_in, ln_g, ln_b,
                                                 sg, W0, as0, ad0);
    k_gat<0><<<ROWS/8, 256>>>(h, bias0, h2, nullptr, nullptr, nullptr);
    k_proj<<<ROWS/32, 256>>>(h2, W1, as1, ad1);
    k_gat<1><<<ROWS/8, 256>>>(nullptr, bias1, nullptr, W_out, b_out, out);
}

// round 7
// speedup vs baseline: 1.8972x; 1.0671x over previous
#include <cuda_runtime.h>
#include <cuda_fp16.h>
#include <math.h>

#define BB   4
#define TT   8
#define NN   2000
#define FIN  158
#define DD   128
#define HH   4
#define CC   32
#define MAXDEG 256
#define SDEG 128
#define ROWS (BB*NN)
#define FRONT_COMPUTE 500            // 16 rows each
#define ADJ_BLOCKS (ROWS/4)          // 4 rows each

// ---------------- device scratch ----------------
__device__ float  g_h  [ROWS*DD];
__device__ float  g_h2 [ROWS*DD];
__device__ __half g_xh [ROWS*DD];    // fp16 aggregation operand
__device__ float4 g_es4[ROWS];
__device__ float4 g_ed4[ROWS];
__device__ int    g_adj[ROWS*MAXDEG];
__device__ int    g_deg[ROWS];

__device__ __forceinline__ void store_half8(__half* dst, float4 v) {
    __half2 p0 = __floats2half2_rn(v.x, v.y);
    __half2 p1 = __floats2half2_rn(v.z, v.w);
    uint2 u;
    u.x = *(unsigned*)&p0; u.y = *(unsigned*)&p1;
    *(uint2*)dst = u;
}

// ============ kernel 1 (fused): (inproj+LN+ReLU -> proj0+att0) || adjacency build ============
__global__ void k_front(const float* __restrict__ x_alpha,
                        const float* __restrict__ W_in,
                        const float* __restrict__ b_in,
                        const float* __restrict__ ln_g,
                        const float* __restrict__ ln_b,
                        const float* __restrict__ sg,
                        const float* __restrict__ W0,
                        const float* __restrict__ as0,
                        const float* __restrict__ ad0)
{
    int tid = threadIdx.x;
    if (blockIdx.x >= FRONT_COMPUTE) {
        // ---- adjacency: 4 rows, 64 threads each ----
        int base = (blockIdx.x - FRONT_COMPUTE) * 4;
        int sub = tid >> 6, c = tid & 63;
        int row = base + sub;
        int i = row % NN;
        __shared__ int cnt[4];
        if (tid < 4) cnt[tid] = 0;
        __syncthreads();
        const float4* rp = (const float4*)(sg + (size_t)row*NN);
        #pragma unroll 2
        for (int t = c; t < NN/4; t += 64) {
            float4 v = rp[t];
            int j0 = 4*t;
            if (v.x > 0.f || j0   == i) { int k = atomicAdd(&cnt[sub],1); if (k < MAXDEG) g_adj[row*MAXDEG+k] = j0;   }
            if (v.y > 0.f || j0+1 == i) { int k = atomicAdd(&cnt[sub],1); if (k < MAXDEG) g_adj[row*MAXDEG+k] = j0+1; }
            if (v.z > 0.f || j0+2 == i) { int k = atomicAdd(&cnt[sub],1); if (k < MAXDEG) g_adj[row*MAXDEG+k] = j0+2; }
            if (v.w > 0.f || j0+3 == i) { int k = atomicAdd(&cnt[sub],1); if (k < MAXDEG) g_adj[row*MAXDEG+k] = j0+3; }
        }
        __syncthreads();
        if (c == 0) g_deg[row] = cnt[sub] < MAXDEG ? cnt[sub] : MAXDEG;
        return;
    }

    // ---- compute blocks ----
    __shared__ float xr[16][FIN];
    __shared__ __align__(16) float sh[16][DD];
    int row0 = blockIdx.x * 16;
    {
        int b = row0 / NN;                    // 16 | NN: blocks never straddle a batch
        const float* xp = x_alpha + (((size_t)b*TT + (TT-1))*NN + (row0 - b*NN))*FIN;
        for (int idx = tid; idx < 16*FIN; idx += 256)
            xr[idx/FIN][idx%FIN] = xp[idx];
    }
    __syncthreads();

    int w = tid >> 5, lane = tid & 31;
    int r0 = 2*w, r1 = 2*w + 1;
    const float* wp = W_in + 4*lane;

    // phase A: h = relu(LN(x@W_in + b_in))
    float4 bi = *(const float4*)(b_in + 4*lane);
    float4 a0 = bi, a1 = bi;
    {
        float4 wv = *(const float4*)wp;
        #pragma unroll 4
        for (int k = 0; k < FIN-1; ++k) {
            float4 wn = *(const float4*)(wp + (size_t)(k+1)*DD);
            float x0 = xr[r0][k], x1 = xr[r1][k];
            a0.x = fmaf(x0, wv.x, a0.x); a0.y = fmaf(x0, wv.y, a0.y);
            a0.z = fmaf(x0, wv.z, a0.z); a0.w = fmaf(x0, wv.w, a0.w);
            a1.x = fmaf(x1, wv.x, a1.x); a1.y = fmaf(x1, wv.y, a1.y);
            a1.z = fmaf(x1, wv.z, a1.z); a1.w = fmaf(x1, wv.w, a1.w);
            wv = wn;
        }
        float x0 = xr[r0][FIN-1], x1 = xr[r1][FIN-1];
        a0.x = fmaf(x0, wv.x, a0.x); a0.y = fmaf(x0, wv.y, a0.y);
        a0.z = fmaf(x0, wv.z, a0.z); a0.w = fmaf(x0, wv.w, a0.w);
        a1.x = fmaf(x1, wv.x, a1.x); a1.y = fmaf(x1, wv.y, a1.y);
        a1.z = fmaf(x1, wv.z, a1.z); a1.w = fmaf(x1, wv.w, a1.w);
    }
    float4 gg = *(const float4*)(ln_g + 4*lane);
    float4 gb = *(const float4*)(ln_b + 4*lane);
    {
        float s = a0.x + a0.y + a0.z + a0.w;
        for (int o = 16; o; o >>= 1) s += __shfl_xor_sync(0xffffffffu, s, o);
        float mean = s * (1.0f/DD);
        float dx=a0.x-mean, dy=a0.y-mean, dz=a0.z-mean, dw=a0.w-mean;
        float q = dx*dx + dy*dy + dz*dz + dw*dw;
        for (int o = 16; o; o >>= 1) q += __shfl_xor_sync(0xffffffffu, q, o);
        float sc = rsqrtf(q * (1.0f/DD) + 1e-5f);
        float4 y;
        y.x = fmaxf(dx*sc*gg.x + gb.x, 0.f); y.y = fmaxf(dy*sc*gg.y + gb.y, 0.f);
        y.z = fmaxf(dz*sc*gg.z + gb.z, 0.f); y.w = fmaxf(dw*sc*gg.w + gb.w, 0.f);
        *(float4*)(g_h + (size_t)(row0+r0)*DD + 4*lane) = y;
        *(float4*)(&sh[r0][4*lane]) = y;
    }
    {
        float s = a1.x + a1.y + a1.z + a1.w;
        for (int o = 16; o; o >>= 1) s += __shfl_xor_sync(0xffffffffu, s, o);
        float mean = s * (1.0f/DD);
        float dx=a1.x-mean, dy=a1.y-mean, dz=a1.z-mean, dw=a1.w-mean;
        float q = dx*dx + dy*dy + dz*dz + dw*dw;
        for (int o = 16; o; o >>= 1) q += __shfl_xor_sync(0xffffffffu, q, o);
        float sc = rsqrtf(q * (1.0f/DD) + 1e-5f);
        float4 y;
        y.x = fmaxf(dx*sc*gg.x + gb.x, 0.f); y.y = fmaxf(dy*sc*gg.y + gb.y, 0.f);
        y.z = fmaxf(dz*sc*gg.z + gb.z, 0.f); y.w = fmaxf(dw*sc*gg.w + gb.w, 0.f);
        *(float4*)(g_h + (size_t)(row0+r1)*DD + 4*lane) = y;
        *(float4*)(&sh[r1][4*lane]) = y;
    }
    __syncthreads();

    // phase B: xh0 = h@W0 (stored fp16) ; e_src/e_dst head-dots (fp32)
    const float* wp0 = W0 + 4*lane;
    float4 c0 = {0,0,0,0}, c1 = {0,0,0,0};
    {
        float4 wv = *(const float4*)wp0;
        #pragma unroll 4
        for (int k = 0; k < DD-1; ++k) {
            float4 wn = *(const float4*)(wp0 + (size_t)(k+1)*DD);
            float x0 = sh[r0][k], x1 = sh[r1][k];
            c0.x = fmaf(x0, wv.x, c0.x); c0.y = fmaf(x0, wv.y, c0.y);
            c0.z = fmaf(x0, wv.z, c0.z); c0.w = fmaf(x0, wv.w, c0.w);
            c1.x = fmaf(x1, wv.x, c1.x); c1.y = fmaf(x1, wv.y, c1.y);
            c1.z = fmaf(x1, wv.z, c1.z); c1.w = fmaf(x1, wv.w, c1.w);
            wv = wn;
        }
        float x0 = sh[r0][DD-1], x1 = sh[r1][DD-1];
        c0.x = fmaf(x0, wv.x, c0.x); c0.y = fmaf(x0, wv.y, c0.y);
        c0.z = fmaf(x0, wv.z, c0.z); c0.w = fmaf(x0, wv.w, c0.w);
        c1.x = fmaf(x1, wv.x, c1.x); c1.y = fmaf(x1, wv.y, c1.y);
        c1.z = fmaf(x1, wv.z, c1.z); c1.w = fmaf(x1, wv.w, c1.w);
    }
    store_half8(g_xh + (size_t)(row0+r0)*DD + 4*lane, c0);
    store_half8(g_xh + (size_t)(row0+r1)*DD + 4*lane, c1);

    float4 av = *(const float4*)(as0 + 4*lane);
    float4 dv = *(const float4*)(ad0 + 4*lane);
    float es0 = c0.x*av.x + c0.y*av.y + c0.z*av.z + c0.w*av.w;
    float ed0 = c0.x*dv.x + c0.y*dv.y + c0.z*dv.z + c0.w*dv.w;
    float es1 = c1.x*av.x + c1.y*av.y + c1.z*av.z + c1.w*av.w;
    float ed1 = c1.x*dv.x + c1.y*dv.y + c1.z*dv.z + c1.w*dv.w;
    for (int o = 4; o; o >>= 1) {
        es0 += __shfl_xor_sync(0xffffffffu, es0, o);
        ed0 += __shfl_xor_sync(0xffffffffu, ed0, o);
        es1 += __shfl_xor_sync(0xffffffffu, es1, o);
        ed1 += __shfl_xor_sync(0xffffffffu, ed1, o);
    }
    if ((lane & 7) == 0) {
        int h = lane >> 3;
        ((float*)(g_es4 + row0 + r0))[h] = es0;
        ((float*)(g_ed4 + row0 + r0))[h] = ed0;
        ((float*)(g_es4 + row0 + r1))[h] = es1;
        ((float*)(g_ed4 + row0 + r1))[h] = ed1;
    }
}

// ============ k_proj (layer 1): xh = h2@W1 (fp16 out) ; e_src/e_dst ============
__global__ void k_proj(const float* __restrict__ hin,
                       const float* __restrict__ W,
                       const float* __restrict__ as_,
                       const float* __restrict__ ad_)
{
    __shared__ __align__(16) float hr[32][DD];
    int row0 = blockIdx.x * 32, tid = threadIdx.x;
    {
        const float4* src = (const float4*)(hin + (size_t)row0*DD);
        float4* dst = (float4*)&hr[0][0];
        #pragma unroll
        for (int i = 0; i < 4; ++i) dst[tid + 256*i] = src[tid + 256*i];
    }
    __syncthreads();

    int w = tid >> 5, lane = tid & 31;
    int r = 4*w;
    const float* wp = W + 4*lane;
    float4 a0={0,0,0,0}, a1=a0, a2=a0, a3=a0;
    float4 wv = *(const float4*)wp;
    #pragma unroll 4
    for (int k = 0; k < DD-1; ++k) {
        float4 wn = *(const float4*)(wp + (size_t)(k+1)*DD);
        float x0=hr[r][k], x1=hr[r+1][k], x2=hr[r+2][k], x3=hr[r+3][k];
        a0.x=fmaf(x0,wv.x,a0.x); a0.y=fmaf(x0,wv.y,a0.y); a0.z=fmaf(x0,wv.z,a0.z); a0.w=fmaf(x0,wv.w,a0.w);
        a1.x=fmaf(x1,wv.x,a1.x); a1.y=fmaf(x1,wv.y,a1.y); a1.z=fmaf(x1,wv.z,a1.z); a1.w=fmaf(x1,wv.w,a1.w);
        a2.x=fmaf(x2,wv.x,a2.x); a2.y=fmaf(x2,wv.y,a2.y); a2.z=fmaf(x2,wv.z,a2.z); a2.w=fmaf(x2,wv.w,a2.w);
        a3.x=fmaf(x3,wv.x,a3.x); a3.y=fmaf(x3,wv.y,a3.y); a3.z=fmaf(x3,wv.z,a3.z); a3.w=fmaf(x3,wv.w,a3.w);
        wv = wn;
    }
    {
        int k = DD-1;
        float x0=hr[r][k], x1=hr[r+1][k], x2=hr[r+2][k], x3=hr[r+3][k];
        a0.x=fmaf(x0,wv.x,a0.x); a0.y=fmaf(x0,wv.y,a0.y); a0.z=fmaf(x0,wv.z,a0.z); a0.w=fmaf(x0,wv.w,a0.w);
        a1.x=fmaf(x1,wv.x,a1.x); a1.y=fmaf(x1,wv.y,a1.y); a1.z=fmaf(x1,wv.z,a1.z); a1.w=fmaf(x1,wv.w,a1.w);
        a2.x=fmaf(x2,wv.x,a2.x); a2.y=fmaf(x2,wv.y,a2.y); a2.z=fmaf(x2,wv.z,a2.z); a2.w=fmaf(x2,wv.w,a2.w);
        a3.x=fmaf(x3,wv.x,a3.x); a3.y=fmaf(x3,wv.y,a3.y); a3.z=fmaf(x3,wv.z,a3.z); a3.w=fmaf(x3,wv.w,a3.w);
    }
    store_half8(g_xh + (size_t)(row0+r  )*DD + 4*lane, a0);
    store_half8(g_xh + (size_t)(row0+r+1)*DD + 4*lane, a1);
    store_half8(g_xh + (size_t)(row0+r+2)*DD + 4*lane, a2);
    store_half8(g_xh + (size_t)(row0+r+3)*DD + 4*lane, a3);

    float4 av = *(const float4*)(as_ + 4*lane);
    float4 dv = *(const float4*)(ad_ + 4*lane);
    float es[4], ed[4];
    es[0]=a0.x*av.x+a0.y*av.y+a0.z*av.z+a0.w*av.w; ed[0]=a0.x*dv.x+a0.y*dv.y+a0.z*dv.z+a0.w*dv.w;
    es[1]=a1.x*av.x+a1.y*av.y+a1.z*av.z+a1.w*av.w; ed[1]=a1.x*dv.x+a1.y*dv.y+a1.z*dv.z+a1.w*dv.w;
    es[2]=a2.x*av.x+a2.y*av.y+a2.z*av.z+a2.w*av.w; ed[2]=a2.x*dv.x+a2.y*dv.y+a2.z*dv.z+a2.w*dv.w;
    es[3]=a3.x*av.x+a3.y*av.y+a3.z*av.z+a3.w*av.w; ed[3]=a3.x*dv.x+a3.y*dv.y+a3.z*dv.z+a3.w*dv.w;
    #pragma unroll
    for (int i = 0; i < 4; ++i)
        for (int o = 4; o; o >>= 1) {
            es[i] += __shfl_xor_sync(0xffffffffu, es[i], o);
            ed[i] += __shfl_xor_sync(0xffffffffu, ed[i], o);
        }
    if ((lane & 7) == 0) {
        int h = lane >> 3;
        #pragma unroll
        for (int i = 0; i < 4; ++i) {
            ((float*)(g_es4 + row0 + r + i))[h] = es[i];
            ((float*)(g_ed4 + row0 + r + i))[h] = ed[i];
        }
    }
}

// ============ k_gat: 4 rows/block, 2 warps/row (parity split), fp16 gather ============
// MODE 0: hout = hin + elu(agg + bias[128])
// MODE 1: out = (head-mean(agg)+bias[32]) @ W_out + b_out
template <int MODE>
__global__ void __launch_bounds__(256) k_gat(
                      const float* __restrict__ hin,
                      const float* __restrict__ bias,
                      float* __restrict__ hout,
                      const float* __restrict__ Wout,
                      const float* __restrict__ bout,
                      float* __restrict__ out)
{
    int tid = threadIdx.x, w = tid >> 5, lane = tid & 31;
    int rsel = w >> 1, p = w & 1;
    int row0 = blockIdx.x * 4;
    int row = row0 + rsel;
    int bN = (row / NN) * NN;

    __shared__ int   soff_s[4][SDEG];
    __shared__ __align__(16) float salp_s[4][SDEG*4];
    __shared__ float ssum_s[4][2][HH];
    __shared__ float sinv_s[4][HH];
    __shared__ __align__(16) float spart_s[4][2][DD];
    __shared__ float shf_s[4][CC];

    int deg = g_deg[row];
    if (deg > SDEG) deg = SDEG;
    float4 edv = g_ed4[row];

    // phase 1: scores -> exp, parity-split over k; per-head partial sums
    float4 sums = {0.f, 0.f, 0.f, 0.f};
    for (int k = p + 2*lane; k < deg; k += 64) {
        int j = g_adj[row*MAXDEG + k];
        soff_s[rsel][k] = (bN + j) * DD;
        float4 es = g_es4[bN + j];
        float4 s;
        s.x = edv.x + es.x; s.x = s.x >= 0.f ? s.x : 0.2f*s.x; s.x = expf(s.x);
        s.y = edv.y + es.y; s.y = s.y >= 0.f ? s.y : 0.2f*s.y; s.y = expf(s.y);
        s.z = edv.z + es.z; s.z = s.z >= 0.f ? s.z : 0.2f*s.z; s.z = expf(s.z);
        s.w = edv.w + es.w; s.w = s.w >= 0.f ? s.w : 0.2f*s.w; s.w = expf(s.w);
        sums.x += s.x; sums.y += s.y; sums.z += s.z; sums.w += s.w;
        *(float4*)(&salp_s[rsel][k*4]) = s;
    }
    for (int o = 16; o; o >>= 1) {
        sums.x += __shfl_xor_sync(0xffffffffu, sums.x, o);
        sums.y += __shfl_xor_sync(0xffffffffu, sums.y, o);
        sums.z += __shfl_xor_sync(0xffffffffu, sums.z, o);
        sums.w += __shfl_xor_sync(0xffffffffu, sums.w, o);
    }
    if (lane == 0) {
        ssum_s[rsel][p][0] = sums.x; ssum_s[rsel][p][1] = sums.y;
        ssum_s[rsel][p][2] = sums.z; ssum_s[rsel][p][3] = sums.w;
    }
    __syncthreads();
    if (p == 0 && lane < HH)
        sinv_s[rsel][lane] = 1.0f / (ssum_s[rsel][0][lane] + ssum_s[rsel][1][lane]);

    // phase 2: gather, parity-split, fp16 rows, MLP 4 per warp
    {
        const __half* base = g_xh + 4*lane;
        const int*   so = soff_s[rsel];
        const float* al = &salp_s[rsel][lane >> 3];
        float4 A0 = {0,0,0,0}, A1 = A0;
        int k = p;
        for (; k + 6 < deg; k += 8) {
            float a0 = al[4*k];       uint2 u0 = *(const uint2*)(base + so[k]);
            float a1 = al[4*(k+2)];   uint2 u1 = *(const uint2*)(base + so[k+2]);
            float a2 = al[4*(k+4)];   uint2 u2 = *(const uint2*)(base + so[k+4]);
            float a3 = al[4*(k+6)];   uint2 u3 = *(const uint2*)(base + so[k+6]);
            float2 f; 
            f = __half22float2(*(__half2*)&u0.x); A0.x=fmaf(a0,f.x,A0.x); A0.y=fmaf(a0,f.y,A0.y);
            f = __half22float2(*(__half2*)&u0.y); A0.z=fmaf(a0,f.x,A0.z); A0.w=fmaf(a0,f.y,A0.w);
            f = __half22float2(*(__half2*)&u1.x); A1.x=fmaf(a1,f.x,A1.x); A1.y=fmaf(a1,f.y,A1.y);
            f = __half22float2(*(__half2*)&u1.y); A1.z=fmaf(a1,f.x,A1.z); A1.w=fmaf(a1,f.y,A1.w);
            f = __half22float2(*(__half2*)&u2.x); A0.x=fmaf(a2,f.x,A0.x); A0.y=fmaf(a2,f.y,A0.y);
            f = __half22float2(*(__half2*)&u2.y); A0.z=fmaf(a2,f.x,A0.z); A0.w=fmaf(a2,f.y,A0.w);
            f = __half22float2(*(__half2*)&u3.x); A1.x=fmaf(a3,f.x,A1.x); A1.y=fmaf(a3,f.y,A1.y);
            f = __half22float2(*(__half2*)&u3.y); A1.z=fmaf(a3,f.x,A1.z); A1.w=fmaf(a3,f.y,A1.w);
        }
        for (; k < deg; k += 2) {
            float a0 = al[4*k];       uint2 u0 = *(const uint2*)(base + so[k]);
            float2 f;
            f = __half22float2(*(__half2*)&u0.x); A0.x=fmaf(a0,f.x,A0.x); A0.y=fmaf(a0,f.y,A0.y);
            f = __half22float2(*(__half2*)&u0.y); A0.z=fmaf(a0,f.x,A0.z); A0.w=fmaf(a0,f.y,A0.w);
        }
        A0.x += A1.x; A0.y += A1.y; A0.z += A1.z; A0.w += A1.w;
        *(float4*)(&spart_s[rsel][p][4*lane]) = A0;
    }
    __syncthreads();

    // phase 3: combine parities, scale by softmax inverse, epilogue
    #pragma unroll
    for (int half = 0; half < 2; ++half) {
        int idx = tid + 256*half;            // 512 = 4 rows x 128 dims
        int r = idx >> 7, d = idx & 127;
        float v = (spart_s[r][0][d] + spart_s[r][1][d]) * sinv_s[r][d >> 5];
        if (MODE == 0) {
            float t = v + bias[d];
            float e = t > 0.f ? t : (expf(t) - 1.f);        // ELU(alpha=1)
            hout[(size_t)(row0+r)*DD + d] = hin[(size_t)(row0+r)*DD + d] + e;
        } else {
            spart_s[r][0][d] = v;                           // reuse as staging
        }
    }
    if (MODE == 1) {
        __syncthreads();
        if (tid < 4*CC) {
            int r = tid >> 5, c = tid & 31;
            shf_s[r][c] = 0.25f * (spart_s[r][0][c] + spart_s[r][0][32+c]
                                 + spart_s[r][0][64+c] + spart_s[r][0][96+c]) + bias[c];
        }
        __syncthreads();
        #pragma unroll
        for (int half = 0; half < 2; ++half) {
            int idx = tid + 256*half;
            int r = idx >> 7, d = idx & 127;
            float acc = bout[d];
            #pragma unroll
            for (int c = 0; c < CC; ++c)
                acc = fmaf(shf_s[r][c], Wout[c*DD + d], acc);
            out[(size_t)(row0+r)*DD + d] = acc;
        }
    }
}

// ---------------- launch ----------------
extern "C" void kernel_launch(void* const* d_in, const int* in_sizes, int n_in,
                              void* d_out, int out_size)
{
    const float* x_alpha = (const float*)d_in[0];
    const float* sg      = (const float*)d_in[1];
    const float* W_in    = (const float*)d_in[2];
    const float* b_in    = (const float*)d_in[3];
    const float* ln_g    = (const float*)d_in[4];
    const float* ln_b    = (const float*)d_in[5];
    const float* W0      = (const float*)d_in[6];
    const float* as0     = (const float*)d_in[7];
    const float* ad0     = (const float*)d_in[8];
    const float* bias0   = (const float*)d_in[9];
    const float* W1      = (const float*)d_in[10];
    const float* as1     = (const float*)d_in[11];
    const float* ad1     = (const float*)d_in[12];
    const float* bias1   = (const float*)d_in[13];
    const float* W_out   = (const float*)d_in[14];
    const float* b_out   = (const float*)d_in[15];
    float* out = (float*)d_out;

    float *h, *h2;
    cudaGetSymbolAddress((void**)&h,  g_h);
    cudaGetSymbolAddress((void**)&h2, g_h2);

    k_front<<<FRONT_COMPUTE + ADJ_BLOCKS, 256>>>(x_alpha, W_in, b_in, ln_g, ln_b,
                                                 sg, W0, as0, ad0);
    k_gat<0><<<ROWS/4, 256>>>(h, bias0, h2, nullptr, nullptr, nullptr);
    k_proj<<<ROWS/32, 256>>>(h2, W1, as1, ad1);
    k_gat<1><<<ROWS/4, 256>>>(nullptr, bias1, nullptr, W_out, b_out, out);
}